// round 15
// baseline (speedup 1.0000x reference)
#include <cuda_runtime.h>
#include <cuda_fp16.h>
#include <cstdint>
#include <math.h>

// Problem constants
#define BB   2
#define LL   2048
#define DD   2048
#define HH   16
#define DHD  128
#define DREL 64
#define KSEL 512
#define MROWS (BB*LL)   // 4096

// -------------------- scratch (device globals; no cudaMalloc allowed) ---------
__device__ __align__(256) __half g_hidh[MROWS*DD];
__device__ __align__(256) __half g_wqh [DD*DD];
__device__ __align__(256) __half g_wkh [DD*DD];
__device__ __align__(256) __half g_wvh [DD*DD];
__device__ __align__(256) __half g_woh [DD*DD];
__device__ __align__(256) __half g_qh  [MROWS*DD];
__device__ __align__(256) __half g_kh  [MROWS*DD];
__device__ __align__(256) __half g_vh  [MROWS*DD];
__device__ __align__(256) __half g_ctxh[MROWS*DD];
__device__ __align__(256) __half g_qrelh[MROWS*DREL];
__device__ __align__(256) __half g_qrell[MROWS*DREL];
__device__ __align__(256) __half g_krelh[MROWS*DREL];
__device__ __align__(256) __half g_krell[MROWS*DREL];
__device__ __align__(256) float    g_scores[(size_t)BB*LL*LL];
__device__ __align__(256) float    g_relp[4*MROWS*128];
__device__ __align__(256) unsigned g_mask[BB*LL*(LL/32)];

// ========================= inline PTX helpers =================================
__device__ __forceinline__ uint32_t smem_u32(const void* p) {
    uint32_t a;
    asm("{ .reg .u64 t; cvta.to.shared.u64 t, %1; cvt.u32.u64 %0, t; }" : "=r"(a) : "l"(p));
    return a;
}
__device__ __forceinline__ void ldsm4(uint32_t* r, uint32_t addr) {
    asm volatile("ldmatrix.sync.aligned.m8n8.x4.shared.b16 {%0,%1,%2,%3}, [%4];"
        : "=r"(r[0]), "=r"(r[1]), "=r"(r[2]), "=r"(r[3]) : "r"(addr));
}
__device__ __forceinline__ void ldsm4t(uint32_t* r, uint32_t addr) {
    asm volatile("ldmatrix.sync.aligned.m8n8.x4.trans.shared.b16 {%0,%1,%2,%3}, [%4];"
        : "=r"(r[0]), "=r"(r[1]), "=r"(r[2]), "=r"(r[3]) : "r"(addr));
}
__device__ __forceinline__ void mma16816(float* c, const uint32_t* a, const uint32_t* b) {
    asm volatile("mma.sync.aligned.m16n8k16.row.col.f32.f16.f16.f32 "
        "{%0,%1,%2,%3}, {%4,%5,%6,%7}, {%8,%9}, {%0,%1,%2,%3};"
        : "+f"(c[0]), "+f"(c[1]), "+f"(c[2]), "+f"(c[3])
        : "r"(a[0]), "r"(a[1]), "r"(a[2]), "r"(a[3]), "r"(b[0]), "r"(b[1]));
}
#define CP_ASYNC16(dst, src) \
    asm volatile("cp.async.cg.shared.global [%0], [%1], 16;" :: "r"(dst), "l"(src) : "memory")
#define CP_ASYNC8(dst, src) \
    asm volatile("cp.async.ca.shared.global [%0], [%1], 8;" :: "r"(dst), "l"(src) : "memory")
#define CP_COMMIT() asm volatile("cp.async.commit_group;" ::: "memory")
#define CP_WAIT(n)  asm volatile("cp.async.wait_group %0;" :: "n"(n) : "memory")

__device__ __forceinline__ float ex2f(float x) {
    float y; asm("ex2.approx.f32 %0, %1;" : "=f"(y) : "f"(x)); return y;
}
__device__ __forceinline__ uint32_t pack_h2(float x, float y) {
    __half hx = __float2half_rn(x), hy = __float2half_rn(y);
    return ((uint32_t)__half_as_ushort(hy) << 16) | __half_as_ushort(hx);
}

// =========================== fp32 -> fp16 conversions =========================
__global__ __launch_bounds__(256) void cvt_hi(
    const float4* __restrict__ x, uint2* __restrict__ h, int n4)
{
    int i = blockIdx.x * 256 + threadIdx.x;
    if (i >= n4) return;
    float4 v = x[i];
    h[i] = make_uint2(pack_h2(v.x, v.y), pack_h2(v.z, v.w));
}

#define N4H (MROWS*DD/4)
#define N4W (DD*DD/4)
__global__ __launch_bounds__(256) void cvt_all(
    const float4* __restrict__ hid, const float4* __restrict__ w0,
    const float4* __restrict__ w1,  const float4* __restrict__ w2,
    uint2* __restrict__ hh, uint2* __restrict__ h0,
    uint2* __restrict__ h1, uint2* __restrict__ h2)
{
    int i = blockIdx.x * 256 + threadIdx.x;
    const float4* src; uint2* dst; int off;
    if (i < N4H)                { src = hid; dst = hh; off = i; }
    else if (i < N4H + N4W)     { src = w0;  dst = h0; off = i - N4H; }
    else if (i < N4H + 2*N4W)   { src = w1;  dst = h1; off = i - N4H - N4W; }
    else if (i < N4H + 3*N4W)   { src = w2;  dst = h2; off = i - N4H - 2*N4W; }
    else return;
    float4 v = src[off];
    dst[off] = make_uint2(pack_h2(v.x, v.y), pack_h2(v.z, v.w));
}

// ===== fp16 GEMM: C = Ah · Bh^T (1-pass) ======================================
// CTA tile 128x256, warp tile 64x64 (8 warps), k-chunk 64, 3-stage cp.async.
#define GROWB 144
#define SEGA64 (128*GROWB)       // 18432
#define SEGB64 (256*GROWB)       // 36864
#define STAGE64 (SEGA64+SEGB64)  // 55296
#define GSMEM (3*STAGE64)        // 165888

template<int OUTMODE>
__device__ __forceinline__ void gemm_body(
    const __half* __restrict__ Ah, const __half* __restrict__ Bh,
    float* __restrict__ Cf, __half* __restrict__ Ch,
    __half* GS)
{
    const uint32_t base = smem_u32(GS);
    const int tid = threadIdx.x;
    const int l   = tid & 31;
    const int wid = tid >> 5;
    const int wm  = wid >> 2;
    const int wn  = wid & 3;
    const int bm  = blockIdx.y * 128;
    const int bn  = blockIdx.x * 256;

    const __half* Ah_p = Ah + (size_t)bm * DD;
    const __half* Bh_p = Bh + (size_t)bn * DD;

    const int rA = wm * 64 + ((l >> 3) & 1) * 8 + (l & 7);
    const int kA = (l >> 4) * 16;
    const int rB = wn * 64 + ((l >> 4) & 1) * 8 + (l & 7);
    const int kB = ((l >> 3) & 1) * 16;

    float acc[4][8][4];
    #pragma unroll
    for (int i = 0; i < 4; i++)
        #pragma unroll
        for (int j = 0; j < 8; j++)
            #pragma unroll
            for (int t = 0; t < 4; t++) acc[i][j][t] = 0.f;

    auto issue_stage = [&](int c, int st) {
        const uint32_t stb = base + (uint32_t)st * STAGE64;
        #pragma unroll
        for (int j = 0; j < 12; j++) {
            int idx = tid + j * 256;
            uint32_t dst; const __half* src;
            if (j < 4) {
                int row = idx >> 3, c16 = idx & 7;
                dst = stb + (uint32_t)row * GROWB + c16 * 16;
                src = Ah_p + (size_t)row * DD + c * 64 + c16 * 8;
            } else {
                int rem = idx - 1024;
                int row = rem >> 3, c16 = rem & 7;
                dst = stb + SEGA64 + (uint32_t)row * GROWB + c16 * 16;
                src = Bh_p + (size_t)row * DD + c * 64 + c16 * 8;
            }
            CP_ASYNC16(dst, src);
        }
        CP_COMMIT();
    };

    issue_stage(0, 0);
    issue_stage(1, 1);

    for (int c = 0; c < DD / 64; c++) {
        CP_WAIT(1);
        __syncthreads();
        if (c + 2 < DD / 64) issue_stage(c + 2, (c + 2) % 3);
        else CP_COMMIT();

        const int st = c % 3;
        const uint32_t sAh = base + (uint32_t)st * STAGE64;
        const uint32_t sBh = sAh + SEGA64;

        #pragma unroll
        for (int ks = 0; ks < 4; ks++) {
            uint32_t aH[4][4];
            #pragma unroll
            for (int mf = 0; mf < 4; mf++)
                ldsm4(aH[mf], sAh + (uint32_t)(rA + mf*16) * GROWB + kA + ks*32);
            #pragma unroll
            for (int nf4 = 0; nf4 < 4; nf4++) {
                uint32_t bH[4];
                ldsm4(bH, sBh + (uint32_t)(rB + nf4*16) * GROWB + kB + ks*32);
                #pragma unroll
                for (int mf = 0; mf < 4; mf++) {
                    mma16816(acc[mf][2*nf4],   aH[mf], bH + 0);
                    mma16816(acc[mf][2*nf4+1], aH[mf], bH + 2);
                }
            }
        }
    }

    const int gid = l >> 2, tig = l & 3;
    #pragma unroll
    for (int mf = 0; mf < 4; mf++) {
        #pragma unroll
        for (int nf = 0; nf < 8; nf++) {
            int r0 = bm + wm*64 + mf*16 + gid;
            int cc = bn + wn*64 + nf*8 + tig*2;
            if (OUTMODE == 2) {
                *(float2*)(Cf + (size_t)r0 * DD + cc)       = make_float2(acc[mf][nf][0], acc[mf][nf][1]);
                *(float2*)(Cf + (size_t)(r0 + 8) * DD + cc) = make_float2(acc[mf][nf][2], acc[mf][nf][3]);
            } else {
                *(uint32_t*)(Ch + (size_t)r0 * DD + cc)       = pack_h2(acc[mf][nf][0], acc[mf][nf][1]);
                *(uint32_t*)(Ch + (size_t)(r0 + 8) * DD + cc) = pack_h2(acc[mf][nf][2], acc[mf][nf][3]);
            }
        }
    }
}

__global__ __launch_bounds__(256) void gemm_qkv(
    const __half* __restrict__ Ah,
    const __half* __restrict__ Wqh, __half* __restrict__ Qh,
    const __half* __restrict__ Wkh, __half* __restrict__ Kh,
    const __half* __restrict__ Wvh, __half* __restrict__ Vh)
{
    extern __shared__ __half GS[];
    if (blockIdx.z == 0)
        gemm_body<1>(Ah, Wqh, nullptr, Qh, GS);
    else if (blockIdx.z == 1)
        gemm_body<1>(Ah, Wkh, nullptr, Kh, GS);
    else
        gemm_body<1>(Ah, Wvh, nullptr, Vh, GS);
}

__global__ __launch_bounds__(256) void gemm_o(
    const __half* __restrict__ Ah,
    const __half* __restrict__ Bh, float* __restrict__ Cf)
{
    extern __shared__ __half GS[];
    gemm_body<2>(Ah, Bh, Cf, nullptr, GS);
}

// ===================== rel projection (split-K, fused q/k) ====================
__global__ __launch_bounds__(256) void rel_proj(
    const float* __restrict__ A, const float* __restrict__ Wq,
    const float* __restrict__ Wk, float* __restrict__ part)
{
    __shared__ __align__(16) float As[32][65];
    __shared__ __align__(16) float Ws[32][132];
    const int tid = threadIdx.x;
    const int m0 = blockIdx.x * 64;
    const int kb = blockIdx.y * 512;
    const int r0 = (tid >> 5) * 8;
    const int c0 = (tid & 31) * 4;

    float acc[8][4];
    #pragma unroll
    for (int i = 0; i < 8; i++)
        #pragma unroll
        for (int j = 0; j < 4; j++) acc[i][j] = 0.f;

    for (int k0 = 0; k0 < 512; k0 += 32) {
        #pragma unroll
        for (int t = 0; t < 2; t++) {
            int idx = tid + t * 256;
            int row = idx >> 3, gg = idx & 7;
            float4 v = *(const float4*)(A + (size_t)(m0 + row) * DD + kb + k0 + gg * 4);
            As[gg*4+0][row] = v.x; As[gg*4+1][row] = v.y;
            As[gg*4+2][row] = v.z; As[gg*4+3][row] = v.w;
        }
        #pragma unroll
        for (int t = 0; t < 4; t++) {
            int idx = tid + t * 256;
            int col = idx >> 3, gg = idx & 7;
            const float* src = (col < 64) ? (Wq + (size_t)col * DD)
                                          : (Wk + (size_t)(col - 64) * DD);
            float4 v = *(const float4*)(src + kb + k0 + gg * 4);
            Ws[gg*4+0][col] = v.x; Ws[gg*4+1][col] = v.y;
            Ws[gg*4+2][col] = v.z; Ws[gg*4+3][col] = v.w;
        }
        __syncthreads();
        #pragma unroll 8
        for (int kk = 0; kk < 32; kk++) {
            float4 w = *(const float4*)&Ws[kk][c0];
            #pragma unroll
            for (int i = 0; i < 8; i++) {
                float a = As[kk][r0 + i];
                acc[i][0] += a * w.x; acc[i][1] += a * w.y;
                acc[i][2] += a * w.z; acc[i][3] += a * w.w;
            }
        }
        __syncthreads();
    }
    float* dst = part + (size_t)blockIdx.y * MROWS * 128;
    #pragma unroll
    for (int i = 0; i < 8; i++) {
        float4 o = make_float4(acc[i][0], acc[i][1], acc[i][2], acc[i][3]);
        *(float4*)(dst + (size_t)(m0 + r0 + i) * 128 + c0) = o;
    }
}

__global__ __launch_bounds__(256) void rel_reduce(
    const float* __restrict__ part,
    __half* __restrict__ qh, __half* __restrict__ ql,
    __half* __restrict__ kh, __half* __restrict__ kl)
{
    int idx = blockIdx.x * 256 + threadIdx.x;
    int row = idx >> 6, col = idx & 63;
    float sq = 0.f, sk = 0.f;
    #pragma unroll
    for (int s = 0; s < 4; s++) {
        const float* p = part + (size_t)s * MROWS * 128 + (size_t)row * 128;
        sq += p[col]; sk += p[col + 64];
    }
    __half hq = __float2half_rn(sq);
    __half hk = __float2half_rn(sk);
    qh[(size_t)row * 64 + col] = hq;
    ql[(size_t)row * 64 + col] = __float2half_rn(sq - __half2float(hq));
    kh[(size_t)row * 64 + col] = hk;
    kl[(size_t)row * 64 + col] = __float2half_rn(sk - __half2float(hk));
}

// ======== rel score GEMM: S[b] = qrel · krel^T (3-pass fp16 split, fp32 out) ==
#define RSTRIDE 144
#define RSEGB (128*RSTRIDE)
#define RSMEM (4*RSEGB)

__global__ __launch_bounds__(256) void score_mma(
    const __half* __restrict__ Qrh, const __half* __restrict__ Qrl,
    const __half* __restrict__ Krh, const __half* __restrict__ Krl,
    float* __restrict__ scores)
{
    const int j = blockIdx.x, i = blockIdx.y, b = blockIdx.z;
    if (j > i) return;
    extern __shared__ __half RS[];
    const uint32_t base = smem_u32(RS);
    const int tid = threadIdx.x;
    const int l = tid & 31, wid = tid >> 5;
    const int wm = wid >> 2, wn = wid & 3;
    const int q0 = i * 128, k0 = j * 128;

    const __half* srcs[4] = {
        Qrh + (size_t)(b*LL + q0) * DREL, Qrl + (size_t)(b*LL + q0) * DREL,
        Krh + (size_t)(b*LL + k0) * DREL, Krl + (size_t)(b*LL + k0) * DREL};

    #pragma unroll
    for (int jj = 0; jj < 16; jj++) {
        int idx = tid + jj * 256;
        int seg = idx >> 10, rem = idx & 1023;
        int row = rem >> 3, c16 = rem & 7;
        uint32_t dst = base + (uint32_t)seg * RSEGB + (uint32_t)row * RSTRIDE + c16 * 16;
        const __half* src = srcs[seg] + (size_t)row * DREL + c16 * 8;
        CP_ASYNC16(dst, src);
    }
    CP_COMMIT();
    CP_WAIT(0);
    __syncthreads();

    const int rA = wm * 64 + ((l >> 3) & 1) * 8 + (l & 7);
    const int kA = (l >> 4) * 16;
    const int rB = wn * 32 + ((l >> 4) & 1) * 8 + (l & 7);
    const int kB = ((l >> 3) & 1) * 16;
    const uint32_t sQh = base, sQl = base + RSEGB;
    const uint32_t sKh = base + 2*RSEGB, sKl = base + 3*RSEGB;

    float acc[4][4][4];
    #pragma unroll
    for (int a = 0; a < 4; a++)
        #pragma unroll
        for (int c = 0; c < 4; c++)
            #pragma unroll
            for (int t = 0; t < 4; t++) acc[a][c][t] = 0.f;

    #pragma unroll
    for (int ks = 0; ks < 4; ks++) {
        uint32_t aH[4][4], aL[4][4];
        #pragma unroll
        for (int mf = 0; mf < 4; mf++) {
            ldsm4(aH[mf], sQh + (uint32_t)(rA + mf*16) * RSTRIDE + kA + ks*32);
            ldsm4(aL[mf], sQl + (uint32_t)(rA + mf*16) * RSTRIDE + kA + ks*32);
        }
        #pragma unroll
        for (int nf2 = 0; nf2 < 2; nf2++) {
            uint32_t bH[4], bL[4];
            ldsm4(bH, sKh + (uint32_t)(rB + nf2*16) * RSTRIDE + kB + ks*32);
            #pragma unroll
            for (int mf = 0; mf < 4; mf++) {
                mma16816(acc[mf][2*nf2],   aH[mf], bH + 0);
                mma16816(acc[mf][2*nf2+1], aH[mf], bH + 2);
                mma16816(acc[mf][2*nf2],   aL[mf], bH + 0);
                mma16816(acc[mf][2*nf2+1], aL[mf], bH + 2);
            }
            ldsm4(bL, sKl + (uint32_t)(rB + nf2*16) * RSTRIDE + kB + ks*32);
            #pragma unroll
            for (int mf = 0; mf < 4; mf++) {
                mma16816(acc[mf][2*nf2],   aH[mf], bL + 0);
                mma16816(acc[mf][2*nf2+1], aH[mf], bL + 2);
            }
        }
    }

    const int gid = l >> 2, tig = l & 3;
    #pragma unroll
    for (int mf = 0; mf < 4; mf++) {
        #pragma unroll
        for (int nf = 0; nf < 4; nf++) {
            int r0 = q0 + wm*64 + mf*16 + gid;
            int cc = k0 + wn*32 + nf*8 + tig*2;
            float* s0p = scores + ((size_t)(b*LL) + r0) * LL + cc;
            *(float2*)s0p            = make_float2(acc[mf][nf][0], acc[mf][nf][1]);
            *(float2*)(s0p + 8 * LL) = make_float2(acc[mf][nf][2], acc[mf][nf][3]);
        }
    }
}

// ====================== top-K mask build (one block per (b,q)) ================
__device__ __forceinline__ unsigned ford(float f) {
    unsigned u = __float_as_uint(f);
    return (u & 0x80000000u) ? ~u : (u | 0x80000000u);
}

__global__ __launch_bounds__(256) void build_mask(
    const float* __restrict__ scores, unsigned* __restrict__ mask)
{
    const int q = blockIdx.x;
    const int b = blockIdx.y;
    const int tid = threadIdx.x;

    __shared__ float    s[LL];
    __shared__ unsigned mw[LL/32];
    __shared__ int      hist[256];
    __shared__ int      scan[256];
    __shared__ unsigned sh_prefix;
    __shared__ int      sh_R;

    if (tid < LL/32) mw[tid] = 0u;
    const int n = q + 1;

    if (n <= KSEL) {
        __syncthreads();
        for (int k = tid; k < n; k += 256)
            atomicOr(&mw[k>>5], 1u << (k & 31));
    } else {
        const float* srow = scores + ((size_t)(b*LL + q)) * LL;
        for (int k = tid; k < n; k += 256) s[k] = srow[k];
        __syncthreads();

        unsigned prefix = 0u; int R = KSEL;
        for (int byte = 3; byte >= 0; byte--) {
            hist[tid] = 0;
            __syncthreads();
            const int shift = byte * 8;
            const unsigned pm = (byte == 3) ? 0u : (0xFFFFFFFFu << (shift + 8));
            for (int k = tid; k < n; k += 256) {
                unsigned u = ford(s[k]);
                if ((u & pm) == (prefix & pm))
                    atomicAdd(&hist[(u >> shift) & 255], 1);
            }
            __syncthreads();
            int hv = hist[tid];
            scan[tid] = hv;
            __syncthreads();
            #pragma unroll
            for (int off = 1; off < 256; off <<= 1) {
                int t = (tid + off < 256) ? scan[tid + off] : 0;
                __syncthreads();
                scan[tid] += t;
                __syncthreads();
            }
            int inc = scan[tid];
            int above = inc - hv;
            if (above < R && inc >= R) {
                sh_prefix = prefix | ((unsigned)tid << shift);
                sh_R = R - above;
            }
            __syncthreads();
            prefix = sh_prefix; R = sh_R;
            __syncthreads();
        }
        const unsigned T = prefix;
        for (int k = tid; k < n; k += 256)
            if (ford(s[k]) > T) atomicOr(&mw[k>>5], 1u << (k & 31));
        const int per = (n + 255) >> 8;
        const int lo = tid * per;
        const int hi = (lo + per < n) ? lo + per : n;
        int cnt = 0;
        for (int k = lo; k < hi; k++)
            if (ford(s[k]) == T) cnt++;
        scan[tid] = cnt;
        __syncthreads();
        #pragma unroll
        for (int off = 1; off < 256; off <<= 1) {
            int t = (tid >= off) ? scan[tid - off] : 0;
            __syncthreads();
            scan[tid] += t;
            __syncthreads();
        }
        int excl = scan[tid] - cnt;
        int r2 = R - excl;
        if (r2 > 0) {
            for (int k = lo; k < hi && r2 > 0; k++)
                if (ford(s[k]) == T) { atomicOr(&mw[k>>5], 1u << (k & 31)); r2--; }
        }
    }
    __syncthreads();
    if (tid == 0) mw[q>>5] |= 1u << (q & 31);
    __syncthreads();
    if (tid < LL/32) mask[(size_t)(b*LL + q)*(LL/32) + tid] = mw[tid];
}

// ====================== flash attention (fp16 mma) ============================
// 8 warps, Q-tile 128 rows (hi), K/V 64 (hi), QK 1-pass, PV 1-pass,
// double-buffered KV, 2 CTAs/SM. KV traffic halved vs 64-row Q-tile.
#define QSEG 17408      // 128*136 halves
#define KSEG 8704       // 64*136 halves
#define FOFF_QH 0
#define KVOFF(st, seg) (QSEG + (st)*2*KSEG + (seg)*KSEG)
#define FMASK_B ((QSEG + 4*KSEG)*2)
#define FSMEM   (FMASK_B + 2*1024)
#define SC2 0.12751744416168355f               // (1/sqrt(128)) * log2(e)

__global__ __launch_bounds__(256) void flash_mma(
    const __half* __restrict__ Qh,
    const __half* __restrict__ Kh, const __half* __restrict__ Vh,
    const unsigned* __restrict__ mask,
    __half* __restrict__ Ch)
{
    extern __shared__ __half FS[];
    const uint32_t base = smem_u32(FS);
    const uint32_t maskB = base + FMASK_B;

    const int qt = (int)gridDim.x - 1 - (int)blockIdx.x;   // heavy tiles first
    const int h = blockIdx.y, b = blockIdx.z;
    const int q0 = qt * 128;
    const int tid = threadIdx.x;
    const int w = tid >> 5, l = tid & 31;
    const int gid = l >> 2, tig = l & 3;

    // Q load (one-time): 128 rows x 16 chunks = 2048 float4 -> 8/thread
    {
        #pragma unroll
        for (int j = 0; j < 8; j++) {
            int idx = tid + j * 256;
            int row = idx >> 4, c16 = idx & 15;
            uint32_t dst = base + (uint32_t)(row * 136 + c16 * 8) * 2;
            const __half* src = Qh + (size_t)(b*LL + q0 + row) * DD + h * DHD + c16 * 8;
            CP_ASYNC16(dst, src);
        }
        CP_COMMIT();
    }

    auto issue_kv = [&](int kt, int st) {
        const __half* ks[2] = {Kh, Vh};
        #pragma unroll
        for (int j = 0; j < 8; j++) {          // 2048 float4
            int idx = tid + j * 256;
            int seg = idx >> 10, rem = idx & 1023;
            int row = rem >> 4, c16 = rem & 15;
            uint32_t dst = base + (uint32_t)(KVOFF(st, seg) + row * 136 + c16 * 8) * 2;
            const __half* src = ks[seg] + (size_t)(b*LL + kt*64 + row) * DD + h * DHD + c16 * 8;
            CP_ASYNC16(dst, src);
        }
        if (tid < 128) {                       // 128 rows x 2 words
            uint32_t dst = maskB + st * 1024 + tid * 8;
            const unsigned* src = &mask[(size_t)(b*LL + q0 + tid) * (LL/32) + kt*2];
            CP_ASYNC8(dst, src);
        }
        CP_COMMIT();
    };

    issue_kv(0, 0);

    const int qa_row = w * 16 + ((l >> 3) & 1) * 8 + (l & 7);
    const int qa_colB = (l >> 4) * 16;
    const int kb_rowBase = ((l >> 4) & 1) * 8 + (l & 7);
    const int kb_colB = ((l >> 3) & 1) * 16;
    const int v_row = l & 15;
    const int v_colB = (l >> 4) * 16;

    float O[16][4];
    #pragma unroll
    for (int i = 0; i < 16; i++)
        #pragma unroll
        for (int t = 0; t < 4; t++) O[i][t] = 0.f;
    float m0 = -1e30f, m1 = -1e30f, rl0 = 0.f, rl1 = 0.f;

    const int rlo2 = (w*16 + gid) * 2;
    const int rhi2 = rlo2 + 16;

    const int ktiles = 2 * qt + 2;
    for (int kt = 0; kt < ktiles; kt++) {
        const int st = kt & 1;
        if (kt + 1 < ktiles) {
            __syncthreads();
            issue_kv(kt + 1, st ^ 1);
            CP_WAIT(1);
        } else {
            CP_WAIT(0);
        }
        __syncthreads();

        const uint32_t sKH = base + (uint32_t)KVOFF(st, 0) * 2;
        const uint32_t sVH = base + (uint32_t)KVOFF(st, 1) * 2;
        const uint32_t* maskS = (const uint32_t*)(FS) + (FMASK_B >> 2) + st * 256;

        // ---- S = Qh Kh^T (1-pass) ----
        float Sc[8][4];
        #pragma unroll
        for (int i = 0; i < 8; i++)
            #pragma unroll
            for (int t = 0; t < 4; t++) Sc[i][t] = 0.f;

        #pragma unroll
        for (int kf = 0; kf < 8; kf++) {
            uint32_t aH[4];
            ldsm4(aH, base + (uint32_t)(FOFF_QH + qa_row * 136) * 2 + kf*32 + qa_colB);
            #pragma unroll
            for (int nf2 = 0; nf2 < 4; nf2++) {
                uint32_t bH[4];
                ldsm4(bH, sKH + (uint32_t)((nf2*16 + kb_rowBase) * 136) * 2 + kf*32 + kb_colB);
                mma16816(Sc[2*nf2],   aH, bH + 0);
                mma16816(Sc[2*nf2+1], aH, bH + 2);
            }
        }

        // ---- mask ----
        #pragma unroll
        for (int nf = 0; nf < 8; nf++) {
            unsigned wlo = maskS[rlo2 + (nf >> 2)];
            unsigned whi = maskS[rhi2 + (nf >> 2)];
            int sh = ((nf & 3) << 3) + (tig << 1);
            Sc[nf][0] = ((wlo >> sh) & 1u)     ? Sc[nf][0] : -1e30f;
            Sc[nf][1] = ((wlo >> (sh+1)) & 1u) ? Sc[nf][1] : -1e30f;
            Sc[nf][2] = ((whi >> sh) & 1u)     ? Sc[nf][2] : -1e30f;
            Sc[nf][3] = ((whi >> (sh+1)) & 1u) ? Sc[nf][3] : -1e30f;
        }

        // ---- online softmax ----
        float mx0 = -1e30f, mx1 = -1e30f;
        #pragma unroll
        for (int nf = 0; nf < 8; nf++) {
            mx0 = fmaxf(mx0, fmaxf(Sc[nf][0], Sc[nf][1]));
            mx1 = fmaxf(mx1, fmaxf(Sc[nf][2], Sc[nf][3]));
        }
        mx0 = fmaxf(mx0, __shfl_xor_sync(0xffffffffu, mx0, 1));
        mx0 = fmaxf(mx0, __shfl_xor_sync(0xffffffffu, mx0, 2));
        mx1 = fmaxf(mx1, __shfl_xor_sync(0xffffffffu, mx1, 1));
        mx1 = fmaxf(mx1, __shfl_xor_sync(0xffffffffu, mx1, 2));
        float nm0 = fmaxf(m0, mx0), nm1 = fmaxf(m1, mx1);
        float a0 = ex2f((m0 - nm0) * SC2), a1 = ex2f((m1 - nm1) * SC2);
        m0 = nm0; m1 = nm1;

        float s0 = 0.f, s1 = 0.f;
        #pragma unroll
        for (int nf = 0; nf < 8; nf++) {
            float p0 = ex2f((Sc[nf][0] - m0) * SC2);
            float p1 = ex2f((Sc[nf][1] - m0) * SC2);
            float p2 = ex2f((Sc[nf][2] - m1) * SC2);
            float p3 = ex2f((Sc[nf][3] - m1) * SC2);
            Sc[nf][0] = p0; Sc[nf][1] = p1; Sc[nf][2] = p2; Sc[nf][3] = p3;
            s0 += p0 + p1; s1 += p2 + p3;
        }
        s0 += __shfl_xor_sync(0xffffffffu, s0, 1);
        s0 += __shfl_xor_sync(0xffffffffu, s0, 2);
        s1 += __shfl_xor_sync(0xffffffffu, s1, 1);
        s1 += __shfl_xor_sync(0xffffffffu, s1, 2);
        rl0 = rl0 * a0 + s0;
        rl1 = rl1 * a1 + s1;

        #pragma unroll
        for (int df = 0; df < 16; df++) {
            O[df][0] *= a0; O[df][1] *= a0;
            O[df][2] *= a1; O[df][3] *= a1;
        }

        // ---- O += P V (1-pass: Ph·Vh) ----
        #pragma unroll
        for (int kf = 0; kf < 4; kf++) {
            uint32_t Pha[4];
            Pha[0] = pack_h2(Sc[2*kf][0],   Sc[2*kf][1]);
            Pha[1] = pack_h2(Sc[2*kf][2],   Sc[2*kf][3]);
            Pha[2] = pack_h2(Sc[2*kf+1][0], Sc[2*kf+1][1]);
            Pha[3] = pack_h2(Sc[2*kf+1][2], Sc[2*kf+1][3]);
            #pragma unroll
            for (int df2 = 0; df2 < 8; df2++) {
                uint32_t vh4[4];
                ldsm4t(vh4, sVH + (uint32_t)((kf*16 + v_row) * 136) * 2 + df2*32 + v_colB);
                mma16816(O[2*df2],   Pha, vh4 + 0);
                mma16816(O[2*df2+1], Pha, vh4 + 2);
            }
        }
    }

    float inv0 = 1.f / rl0, inv1 = 1.f / rl1;
    const size_t rowlo = (size_t)(b*LL + q0 + w*16 + gid) * DD + h * DHD + tig * 2;
    const size_t rowhi = rowlo + 8 * DD;
    #pragma unroll
    for (int df = 0; df < 16; df++) {
        *(uint32_t*)(Ch + rowlo + df*8) = pack_h2(O[df][0] * inv0, O[df][1] * inv0);
        *(uint32_t*)(Ch + rowhi + df*8) = pack_h2(O[df][2] * inv1, O[df][3] * inv1);
    }
}

// ================================ launch ======================================
extern "C" void kernel_launch(void* const* d_in, const int* in_sizes, int n_in,
                              void* d_out, int out_size)
{
    const float* hidden    = (const float*)d_in[0];
    const float* relevance = (const float*)d_in[1];
    const float* Wqr       = (const float*)d_in[2];
    const float* Wkr       = (const float*)d_in[3];
    const float* Wq        = (const float*)d_in[4];
    const float* Wk        = (const float*)d_in[5];
    const float* Wv        = (const float*)d_in[6];
    const float* Wo        = (const float*)d_in[7];
    float* out = (float*)d_out;

    __half *hidh,*wqh,*wkh,*wvh,*woh;
    __half *qh,*kh,*vh,*ctxh;
    __half *qrelh,*qrell,*krelh,*krell;
    float *relp,*scores; unsigned* mask;
    cudaGetSymbolAddress((void**)&hidh, g_hidh);
    cudaGetSymbolAddress((void**)&wqh,  g_wqh);
    cudaGetSymbolAddress((void**)&wkh,  g_wkh);
    cudaGetSymbolAddress((void**)&wvh,  g_wvh);
    cudaGetSymbolAddress((void**)&woh,  g_woh);
    cudaGetSymbolAddress((void**)&qh,   g_qh);
    cudaGetSymbolAddress((void**)&kh,   g_kh);
    cudaGetSymbolAddress((void**)&vh,   g_vh);
    cudaGetSymbolAddress((void**)&ctxh, g_ctxh);
    cudaGetSymbolAddress((void**)&qrelh, g_qrelh); cudaGetSymbolAddress((void**)&qrell, g_qrell);
    cudaGetSymbolAddress((void**)&krelh, g_krelh); cudaGetSymbolAddress((void**)&krell, g_krell);
    cudaGetSymbolAddress((void**)&scores, g_scores);
    cudaGetSymbolAddress((void**)&relp, g_relp); cudaGetSymbolAddress((void**)&mask, g_mask);

    cudaFuncSetAttribute(gemm_qkv, cudaFuncAttributeMaxDynamicSharedMemorySize, GSMEM);
    cudaFuncSetAttribute(gemm_o,   cudaFuncAttributeMaxDynamicSharedMemorySize, GSMEM);
    cudaFuncSetAttribute(flash_mma, cudaFuncAttributeMaxDynamicSharedMemorySize, FSMEM);
    cudaFuncSetAttribute(score_mma, cudaFuncAttributeMaxDynamicSharedMemorySize, RSMEM);

    static cudaStream_t sSide = nullptr;
    static cudaEvent_t  evFork = nullptr, evJoin = nullptr;
    if (sSide == nullptr) {
        cudaStreamCreateWithFlags(&sSide, cudaStreamNonBlocking);
        cudaEventCreateWithFlags(&evFork, cudaEventDisableTiming);
        cudaEventCreateWithFlags(&evJoin, cudaEventDisableTiming);
    }

    const int nw4 = DD * DD / 4;
    const int nAll = N4H + 3 * N4W;

    // ---- fork: relevance/mask path (+ Wo cvt) on side stream ----
    cudaEventRecord(evFork, 0);
    cudaStreamWaitEvent(sSide, evFork, 0);
    rel_proj<<<dim3(MROWS/64, 4), 256, 0, sSide>>>(relevance, Wqr, Wkr, relp);
    rel_reduce<<<(MROWS*64)/256, 256, 0, sSide>>>(relp, qrelh, qrell, krelh, krell);
    score_mma<<<dim3(16, 16, BB), 256, RSMEM, sSide>>>(qrelh, qrell, krelh, krell, scores);
    build_mask<<<dim3(LL, BB), 256, 0, sSide>>>(scores, mask);
    cvt_hi<<<(nw4 + 255)/256, 256, 0, sSide>>>((const float4*)Wo, (uint2*)woh, nw4);
    cudaEventRecord(evJoin, sSide);

    // ---- main stream: merged conversion + QKV ----
    cvt_all<<<(nAll + 255)/256, 256>>>(
        (const float4*)hidden, (const float4*)Wq, (const float4*)Wk, (const float4*)Wv,
        (uint2*)hidh, (uint2*)wqh, (uint2*)wkh, (uint2*)wvh);

    gemm_qkv<<<dim3(DD/256, MROWS/128, 3), 256, GSMEM>>>(
        hidh, wqh, qh, wkh, kh, wvh, vh);

    // ---- join, then attention + output projection ----
    cudaStreamWaitEvent(0, evJoin, 0);
    flash_mma<<<dim3(LL/128, HH, BB), 256, FSMEM>>>(qh, kh, vh, mask, ctxh);
    gemm_o<<<dim3(DD/256, MROWS/128), 256, GSMEM>>>(ctxh, woh, out);
}

// round 16
// speedup vs baseline: 1.0693x; 1.0693x over previous
#include <cuda_runtime.h>
#include <cuda_fp16.h>
#include <cstdint>
#include <math.h>

// Problem constants
#define BB   2
#define LL   2048
#define DD   2048
#define HH   16
#define DHD  128
#define DREL 64
#define KSEL 512
#define MROWS (BB*LL)   // 4096

// -------------------- scratch (device globals; no cudaMalloc allowed) ---------
__device__ __align__(256) __half g_hidh[MROWS*DD];
__device__ __align__(256) __half g_wqh [DD*DD];
__device__ __align__(256) __half g_wkh [DD*DD];
__device__ __align__(256) __half g_wvh [DD*DD];
__device__ __align__(256) __half g_woh [DD*DD];
__device__ __align__(256) __half g_qh  [MROWS*DD];
__device__ __align__(256) __half g_kh  [MROWS*DD];
__device__ __align__(256) __half g_vh  [MROWS*DD];
__device__ __align__(256) __half g_ctxh[MROWS*DD];
__device__ __align__(256) __half g_qrelh[MROWS*DREL];
__device__ __align__(256) __half g_qrell[MROWS*DREL];
__device__ __align__(256) __half g_krelh[MROWS*DREL];
__device__ __align__(256) __half g_krell[MROWS*DREL];
__device__ __align__(256) float    g_scores[(size_t)BB*LL*LL];
__device__ __align__(256) float    g_relp[4*MROWS*128];
__device__ __align__(256) unsigned g_mask[BB*LL*(LL/32)];

// ========================= inline PTX helpers =================================
__device__ __forceinline__ uint32_t smem_u32(const void* p) {
    uint32_t a;
    asm("{ .reg .u64 t; cvta.to.shared.u64 t, %1; cvt.u32.u64 %0, t; }" : "=r"(a) : "l"(p));
    return a;
}
__device__ __forceinline__ void ldsm4(uint32_t* r, uint32_t addr) {
    asm volatile("ldmatrix.sync.aligned.m8n8.x4.shared.b16 {%0,%1,%2,%3}, [%4];"
        : "=r"(r[0]), "=r"(r[1]), "=r"(r[2]), "=r"(r[3]) : "r"(addr));
}
__device__ __forceinline__ void ldsm4t(uint32_t* r, uint32_t addr) {
    asm volatile("ldmatrix.sync.aligned.m8n8.x4.trans.shared.b16 {%0,%1,%2,%3}, [%4];"
        : "=r"(r[0]), "=r"(r[1]), "=r"(r[2]), "=r"(r[3]) : "r"(addr));
}
__device__ __forceinline__ void mma16816(float* c, const uint32_t* a, const uint32_t* b) {
    asm volatile("mma.sync.aligned.m16n8k16.row.col.f32.f16.f16.f32 "
        "{%0,%1,%2,%3}, {%4,%5,%6,%7}, {%8,%9}, {%0,%1,%2,%3};"
        : "+f"(c[0]), "+f"(c[1]), "+f"(c[2]), "+f"(c[3])
        : "r"(a[0]), "r"(a[1]), "r"(a[2]), "r"(a[3]), "r"(b[0]), "r"(b[1]));
}
#define CP_ASYNC16(dst, src) \
    asm volatile("cp.async.cg.shared.global [%0], [%1], 16;" :: "r"(dst), "l"(src) : "memory")
#define CP_ASYNC8(dst, src) \
    asm volatile("cp.async.ca.shared.global [%0], [%1], 8;" :: "r"(dst), "l"(src) : "memory")
#define CP_COMMIT() asm volatile("cp.async.commit_group;" ::: "memory")
#define CP_WAIT(n)  asm volatile("cp.async.wait_group %0;" :: "n"(n) : "memory")

__device__ __forceinline__ float ex2f(float x) {
    float y; asm("ex2.approx.f32 %0, %1;" : "=f"(y) : "f"(x)); return y;
}
__device__ __forceinline__ uint32_t pack_h2(float x, float y) {
    __half hx = __float2half_rn(x), hy = __float2half_rn(y);
    return ((uint32_t)__half_as_ushort(hy) << 16) | __half_as_ushort(hx);
}

// =========================== fp32 -> fp16 conversions =========================
__global__ __launch_bounds__(256) void cvt_hi(
    const float4* __restrict__ x, uint2* __restrict__ h, int n4)
{
    int i = blockIdx.x * 256 + threadIdx.x;
    if (i >= n4) return;
    float4 v = x[i];
    h[i] = make_uint2(pack_h2(v.x, v.y), pack_h2(v.z, v.w));
}

#define N4H (MROWS*DD/4)
#define N4W (DD*DD/4)
__global__ __launch_bounds__(256) void cvt_all(
    const float4* __restrict__ hid, const float4* __restrict__ w0,
    const float4* __restrict__ w1,  const float4* __restrict__ w2,
    uint2* __restrict__ hh, uint2* __restrict__ h0,
    uint2* __restrict__ h1, uint2* __restrict__ h2)
{
    int i = blockIdx.x * 256 + threadIdx.x;
    const float4* src; uint2* dst; int off;
    if (i < N4H)                { src = hid; dst = hh; off = i; }
    else if (i < N4H + N4W)     { src = w0;  dst = h0; off = i - N4H; }
    else if (i < N4H + 2*N4W)   { src = w1;  dst = h1; off = i - N4H - N4W; }
    else if (i < N4H + 3*N4W)   { src = w2;  dst = h2; off = i - N4H - 2*N4W; }
    else return;
    float4 v = src[off];
    dst[off] = make_uint2(pack_h2(v.x, v.y), pack_h2(v.z, v.w));
}

// ===== fp16 GEMM: C = Ah · Bh^T (1-pass) ======================================
// CTA tile 128x256, warp tile 64x64 (8 warps), k-chunk 64, 3-stage cp.async.
#define GROWB 144
#define SEGA64 (128*GROWB)       // 18432
#define SEGB64 (256*GROWB)       // 36864
#define STAGE64 (SEGA64+SEGB64)  // 55296
#define GSMEM (3*STAGE64)        // 165888

template<int OUTMODE>
__device__ __forceinline__ void gemm_body(
    const __half* __restrict__ Ah, const __half* __restrict__ Bh,
    float* __restrict__ Cf, __half* __restrict__ Ch,
    __half* GS)
{
    const uint32_t base = smem_u32(GS);
    const int tid = threadIdx.x;
    const int l   = tid & 31;
    const int wid = tid >> 5;
    const int wm  = wid >> 2;
    const int wn  = wid & 3;
    const int bm  = blockIdx.y * 128;
    const int bn  = blockIdx.x * 256;

    const __half* Ah_p = Ah + (size_t)bm * DD;
    const __half* Bh_p = Bh + (size_t)bn * DD;

    const int rA = wm * 64 + ((l >> 3) & 1) * 8 + (l & 7);
    const int kA = (l >> 4) * 16;
    const int rB = wn * 64 + ((l >> 4) & 1) * 8 + (l & 7);
    const int kB = ((l >> 3) & 1) * 16;

    float acc[4][8][4];
    #pragma unroll
    for (int i = 0; i < 4; i++)
        #pragma unroll
        for (int j = 0; j < 8; j++)
            #pragma unroll
            for (int t = 0; t < 4; t++) acc[i][j][t] = 0.f;

    auto issue_stage = [&](int c, int st) {
        const uint32_t stb = base + (uint32_t)st * STAGE64;
        #pragma unroll
        for (int j = 0; j < 12; j++) {
            int idx = tid + j * 256;
            uint32_t dst; const __half* src;
            if (j < 4) {
                int row = idx >> 3, c16 = idx & 7;
                dst = stb + (uint32_t)row * GROWB + c16 * 16;
                src = Ah_p + (size_t)row * DD + c * 64 + c16 * 8;
            } else {
                int rem = idx - 1024;
                int row = rem >> 3, c16 = rem & 7;
                dst = stb + SEGA64 + (uint32_t)row * GROWB + c16 * 16;
                src = Bh_p + (size_t)row * DD + c * 64 + c16 * 8;
            }
            CP_ASYNC16(dst, src);
        }
        CP_COMMIT();
    };

    issue_stage(0, 0);
    issue_stage(1, 1);

    for (int c = 0; c < DD / 64; c++) {
        CP_WAIT(1);
        __syncthreads();
        if (c + 2 < DD / 64) issue_stage(c + 2, (c + 2) % 3);
        else CP_COMMIT();

        const int st = c % 3;
        const uint32_t sAh = base + (uint32_t)st * STAGE64;
        const uint32_t sBh = sAh + SEGA64;

        #pragma unroll
        for (int ks = 0; ks < 4; ks++) {
            uint32_t aH[4][4];
            #pragma unroll
            for (int mf = 0; mf < 4; mf++)
                ldsm4(aH[mf], sAh + (uint32_t)(rA + mf*16) * GROWB + kA + ks*32);
            #pragma unroll
            for (int nf4 = 0; nf4 < 4; nf4++) {
                uint32_t bH[4];
                ldsm4(bH, sBh + (uint32_t)(rB + nf4*16) * GROWB + kB + ks*32);
                #pragma unroll
                for (int mf = 0; mf < 4; mf++) {
                    mma16816(acc[mf][2*nf4],   aH[mf], bH + 0);
                    mma16816(acc[mf][2*nf4+1], aH[mf], bH + 2);
                }
            }
        }
    }

    const int gid = l >> 2, tig = l & 3;
    #pragma unroll
    for (int mf = 0; mf < 4; mf++) {
        #pragma unroll
        for (int nf = 0; nf < 8; nf++) {
            int r0 = bm + wm*64 + mf*16 + gid;
            int cc = bn + wn*64 + nf*8 + tig*2;
            if (OUTMODE == 2) {
                *(float2*)(Cf + (size_t)r0 * DD + cc)       = make_float2(acc[mf][nf][0], acc[mf][nf][1]);
                *(float2*)(Cf + (size_t)(r0 + 8) * DD + cc) = make_float2(acc[mf][nf][2], acc[mf][nf][3]);
            } else {
                *(uint32_t*)(Ch + (size_t)r0 * DD + cc)       = pack_h2(acc[mf][nf][0], acc[mf][nf][1]);
                *(uint32_t*)(Ch + (size_t)(r0 + 8) * DD + cc) = pack_h2(acc[mf][nf][2], acc[mf][nf][3]);
            }
        }
    }
}

__global__ __launch_bounds__(256) void gemm_qkv(
    const __half* __restrict__ Ah,
    const __half* __restrict__ Wqh, __half* __restrict__ Qh,
    const __half* __restrict__ Wkh, __half* __restrict__ Kh,
    const __half* __restrict__ Wvh, __half* __restrict__ Vh)
{
    extern __shared__ __half GS[];
    if (blockIdx.z == 0)
        gemm_body<1>(Ah, Wqh, nullptr, Qh, GS);
    else if (blockIdx.z == 1)
        gemm_body<1>(Ah, Wkh, nullptr, Kh, GS);
    else
        gemm_body<1>(Ah, Wvh, nullptr, Vh, GS);
}

__global__ __launch_bounds__(256) void gemm_o(
    const __half* __restrict__ Ah,
    const __half* __restrict__ Bh, float* __restrict__ Cf)
{
    extern __shared__ __half GS[];
    gemm_body<2>(Ah, Bh, Cf, nullptr, GS);
}

// ===================== rel projection (split-K, fused q/k) ====================
__global__ __launch_bounds__(256) void rel_proj(
    const float* __restrict__ A, const float* __restrict__ Wq,
    const float* __restrict__ Wk, float* __restrict__ part)
{
    __shared__ __align__(16) float As[32][65];
    __shared__ __align__(16) float Ws[32][132];
    const int tid = threadIdx.x;
    const int m0 = blockIdx.x * 64;
    const int kb = blockIdx.y * 512;
    const int r0 = (tid >> 5) * 8;
    const int c0 = (tid & 31) * 4;

    float acc[8][4];
    #pragma unroll
    for (int i = 0; i < 8; i++)
        #pragma unroll
        for (int j = 0; j < 4; j++) acc[i][j] = 0.f;

    for (int k0 = 0; k0 < 512; k0 += 32) {
        #pragma unroll
        for (int t = 0; t < 2; t++) {
            int idx = tid + t * 256;
            int row = idx >> 3, gg = idx & 7;
            float4 v = *(const float4*)(A + (size_t)(m0 + row) * DD + kb + k0 + gg * 4);
            As[gg*4+0][row] = v.x; As[gg*4+1][row] = v.y;
            As[gg*4+2][row] = v.z; As[gg*4+3][row] = v.w;
        }
        #pragma unroll
        for (int t = 0; t < 4; t++) {
            int idx = tid + t * 256;
            int col = idx >> 3, gg = idx & 7;
            const float* src = (col < 64) ? (Wq + (size_t)col * DD)
                                          : (Wk + (size_t)(col - 64) * DD);
            float4 v = *(const float4*)(src + kb + k0 + gg * 4);
            Ws[gg*4+0][col] = v.x; Ws[gg*4+1][col] = v.y;
            Ws[gg*4+2][col] = v.z; Ws[gg*4+3][col] = v.w;
        }
        __syncthreads();
        #pragma unroll 8
        for (int kk = 0; kk < 32; kk++) {
            float4 w = *(const float4*)&Ws[kk][c0];
            #pragma unroll
            for (int i = 0; i < 8; i++) {
                float a = As[kk][r0 + i];
                acc[i][0] += a * w.x; acc[i][1] += a * w.y;
                acc[i][2] += a * w.z; acc[i][3] += a * w.w;
            }
        }
        __syncthreads();
    }
    float* dst = part + (size_t)blockIdx.y * MROWS * 128;
    #pragma unroll
    for (int i = 0; i < 8; i++) {
        float4 o = make_float4(acc[i][0], acc[i][1], acc[i][2], acc[i][3]);
        *(float4*)(dst + (size_t)(m0 + r0 + i) * 128 + c0) = o;
    }
}

__global__ __launch_bounds__(256) void rel_reduce(
    const float* __restrict__ part,
    __half* __restrict__ qh, __half* __restrict__ ql,
    __half* __restrict__ kh, __half* __restrict__ kl)
{
    int idx = blockIdx.x * 256 + threadIdx.x;
    int row = idx >> 6, col = idx & 63;
    float sq = 0.f, sk = 0.f;
    #pragma unroll
    for (int s = 0; s < 4; s++) {
        const float* p = part + (size_t)s * MROWS * 128 + (size_t)row * 128;
        sq += p[col]; sk += p[col + 64];
    }
    __half hq = __float2half_rn(sq);
    __half hk = __float2half_rn(sk);
    qh[(size_t)row * 64 + col] = hq;
    ql[(size_t)row * 64 + col] = __float2half_rn(sq - __half2float(hq));
    kh[(size_t)row * 64 + col] = hk;
    kl[(size_t)row * 64 + col] = __float2half_rn(sk - __half2float(hk));
}

// ======== rel score GEMM: S[b] = qrel · krel^T (3-pass fp16 split, fp32 out) ==
#define RSTRIDE 144
#define RSEGB (128*RSTRIDE)
#define RSMEM (4*RSEGB)

__global__ __launch_bounds__(256) void score_mma(
    const __half* __restrict__ Qrh, const __half* __restrict__ Qrl,
    const __half* __restrict__ Krh, const __half* __restrict__ Krl,
    float* __restrict__ scores)
{
    const int j = blockIdx.x, i = blockIdx.y, b = blockIdx.z;
    if (j > i) return;
    extern __shared__ __half RS[];
    const uint32_t base = smem_u32(RS);
    const int tid = threadIdx.x;
    const int l = tid & 31, wid = tid >> 5;
    const int wm = wid >> 2, wn = wid & 3;
    const int q0 = i * 128, k0 = j * 128;

    const __half* srcs[4] = {
        Qrh + (size_t)(b*LL + q0) * DREL, Qrl + (size_t)(b*LL + q0) * DREL,
        Krh + (size_t)(b*LL + k0) * DREL, Krl + (size_t)(b*LL + k0) * DREL};

    #pragma unroll
    for (int jj = 0; jj < 16; jj++) {
        int idx = tid + jj * 256;
        int seg = idx >> 10, rem = idx & 1023;
        int row = rem >> 3, c16 = rem & 7;
        uint32_t dst = base + (uint32_t)seg * RSEGB + (uint32_t)row * RSTRIDE + c16 * 16;
        const __half* src = srcs[seg] + (size_t)row * DREL + c16 * 8;
        CP_ASYNC16(dst, src);
    }
    CP_COMMIT();
    CP_WAIT(0);
    __syncthreads();

    const int rA = wm * 64 + ((l >> 3) & 1) * 8 + (l & 7);
    const int kA = (l >> 4) * 16;
    const int rB = wn * 32 + ((l >> 4) & 1) * 8 + (l & 7);
    const int kB = ((l >> 3) & 1) * 16;
    const uint32_t sQh = base, sQl = base + RSEGB;
    const uint32_t sKh = base + 2*RSEGB, sKl = base + 3*RSEGB;

    float acc[4][4][4];
    #pragma unroll
    for (int a = 0; a < 4; a++)
        #pragma unroll
        for (int c = 0; c < 4; c++)
            #pragma unroll
            for (int t = 0; t < 4; t++) acc[a][c][t] = 0.f;

    #pragma unroll
    for (int ks = 0; ks < 4; ks++) {
        uint32_t aH[4][4], aL[4][4];
        #pragma unroll
        for (int mf = 0; mf < 4; mf++) {
            ldsm4(aH[mf], sQh + (uint32_t)(rA + mf*16) * RSTRIDE + kA + ks*32);
            ldsm4(aL[mf], sQl + (uint32_t)(rA + mf*16) * RSTRIDE + kA + ks*32);
        }
        #pragma unroll
        for (int nf2 = 0; nf2 < 2; nf2++) {
            uint32_t bH[4], bL[4];
            ldsm4(bH, sKh + (uint32_t)(rB + nf2*16) * RSTRIDE + kB + ks*32);
            #pragma unroll
            for (int mf = 0; mf < 4; mf++) {
                mma16816(acc[mf][2*nf2],   aH[mf], bH + 0);
                mma16816(acc[mf][2*nf2+1], aH[mf], bH + 2);
                mma16816(acc[mf][2*nf2],   aL[mf], bH + 0);
                mma16816(acc[mf][2*nf2+1], aL[mf], bH + 2);
            }
            ldsm4(bL, sKl + (uint32_t)(rB + nf2*16) * RSTRIDE + kB + ks*32);
            #pragma unroll
            for (int mf = 0; mf < 4; mf++) {
                mma16816(acc[mf][2*nf2],   aH[mf], bL + 0);
                mma16816(acc[mf][2*nf2+1], aH[mf], bL + 2);
            }
        }
    }

    const int gid = l >> 2, tig = l & 3;
    #pragma unroll
    for (int mf = 0; mf < 4; mf++) {
        #pragma unroll
        for (int nf = 0; nf < 4; nf++) {
            int r0 = q0 + wm*64 + mf*16 + gid;
            int cc = k0 + wn*32 + nf*8 + tig*2;
            float* s0p = scores + ((size_t)(b*LL) + r0) * LL + cc;
            *(float2*)s0p            = make_float2(acc[mf][nf][0], acc[mf][nf][1]);
            *(float2*)(s0p + 8 * LL) = make_float2(acc[mf][nf][2], acc[mf][nf][3]);
        }
    }
}

// ====================== top-K mask build (one block per (b,q)) ================
__device__ __forceinline__ unsigned ford(float f) {
    unsigned u = __float_as_uint(f);
    return (u & 0x80000000u) ? ~u : (u | 0x80000000u);
}

__global__ __launch_bounds__(256) void build_mask(
    const float* __restrict__ scores, unsigned* __restrict__ mask)
{
    const int q = blockIdx.x;
    const int b = blockIdx.y;
    const int tid = threadIdx.x;

    __shared__ float    s[LL];
    __shared__ unsigned mw[LL/32];
    __shared__ int      hist[256];
    __shared__ int      scan[256];
    __shared__ unsigned sh_prefix;
    __shared__ int      sh_R;

    if (tid < LL/32) mw[tid] = 0u;
    const int n = q + 1;

    if (n <= KSEL) {
        __syncthreads();
        for (int k = tid; k < n; k += 256)
            atomicOr(&mw[k>>5], 1u << (k & 31));
    } else {
        const float* srow = scores + ((size_t)(b*LL + q)) * LL;
        for (int k = tid; k < n; k += 256) s[k] = srow[k];
        __syncthreads();

        unsigned prefix = 0u; int R = KSEL;
        for (int byte = 3; byte >= 0; byte--) {
            hist[tid] = 0;
            __syncthreads();
            const int shift = byte * 8;
            const unsigned pm = (byte == 3) ? 0u : (0xFFFFFFFFu << (shift + 8));
            for (int k = tid; k < n; k += 256) {
                unsigned u = ford(s[k]);
                if ((u & pm) == (prefix & pm))
                    atomicAdd(&hist[(u >> shift) & 255], 1);
            }
            __syncthreads();
            int hv = hist[tid];
            scan[tid] = hv;
            __syncthreads();
            #pragma unroll
            for (int off = 1; off < 256; off <<= 1) {
                int t = (tid + off < 256) ? scan[tid + off] : 0;
                __syncthreads();
                scan[tid] += t;
                __syncthreads();
            }
            int inc = scan[tid];
            int above = inc - hv;
            if (above < R && inc >= R) {
                sh_prefix = prefix | ((unsigned)tid << shift);
                sh_R = R - above;
            }
            __syncthreads();
            prefix = sh_prefix; R = sh_R;
            __syncthreads();
        }
        const unsigned T = prefix;
        for (int k = tid; k < n; k += 256)
            if (ford(s[k]) > T) atomicOr(&mw[k>>5], 1u << (k & 31));
        const int per = (n + 255) >> 8;
        const int lo = tid * per;
        const int hi = (lo + per < n) ? lo + per : n;
        int cnt = 0;
        for (int k = lo; k < hi; k++)
            if (ford(s[k]) == T) cnt++;
        scan[tid] = cnt;
        __syncthreads();
        #pragma unroll
        for (int off = 1; off < 256; off <<= 1) {
            int t = (tid >= off) ? scan[tid - off] : 0;
            __syncthreads();
            scan[tid] += t;
            __syncthreads();
        }
        int excl = scan[tid] - cnt;
        int r2 = R - excl;
        if (r2 > 0) {
            for (int k = lo; k < hi && r2 > 0; k++)
                if (ford(s[k]) == T) { atomicOr(&mw[k>>5], 1u << (k & 31)); r2--; }
        }
    }
    __syncthreads();
    if (tid == 0) mw[q>>5] |= 1u << (q & 31);
    __syncthreads();
    if (tid < LL/32) mask[(size_t)(b*LL + q)*(LL/32) + tid] = mw[tid];
}

// ====================== flash attention (fp16 mma) ============================
// 4 warps, Q-tile 64 (hi), K/V 64 (hi), QK 1-pass, PV 1-pass,
// double-buffered KV, 2 CTAs/SM (cross-CTA phase overlap).
#define QSEG 8704       // 64*136 halves
#define KSEG 8704
#define FOFF_QH 0
#define KVOFF(st, seg) (QSEG + (st)*2*KSEG + (seg)*KSEG)
#define FMASK_B ((QSEG + 4*KSEG)*2)
#define FSMEM   (FMASK_B + 2*512)
#define SC2 0.12751744416168355f               // (1/sqrt(128)) * log2(e)

__global__ __launch_bounds__(128) void flash_mma(
    const __half* __restrict__ Qh,
    const __half* __restrict__ Kh, const __half* __restrict__ Vh,
    const unsigned* __restrict__ mask,
    __half* __restrict__ Ch)
{
    extern __shared__ __half FS[];
    const uint32_t base = smem_u32(FS);
    const uint32_t maskB = base + FMASK_B;

    const int qt = (int)gridDim.x - 1 - (int)blockIdx.x;   // heavy tiles first
    const int h = blockIdx.y, b = blockIdx.z;
    const int q0 = qt * 64;
    const int tid = threadIdx.x;
    const int w = tid >> 5, l = tid & 31;
    const int gid = l >> 2, tig = l & 3;

    // Q load (one-time)
    {
        #pragma unroll
        for (int j = 0; j < 8; j++) {
            int idx = tid + j * 128;
            int row = idx >> 4, c16 = idx & 15;
            uint32_t dst = base + (uint32_t)(row * 136 + c16 * 8) * 2;
            const __half* src = Qh + (size_t)(b*LL + q0 + row) * DD + h * DHD + c16 * 8;
            CP_ASYNC16(dst, src);
        }
        CP_COMMIT();
    }

    auto issue_kv = [&](int kt, int st) {
        const __half* ks[2] = {Kh, Vh};
        #pragma unroll
        for (int j = 0; j < 16; j++) {
            int idx = tid + j * 128;
            int seg = idx >> 10, rem = idx & 1023;
            int row = rem >> 4, c16 = rem & 15;
            uint32_t dst = base + (uint32_t)(KVOFF(st, seg) + row * 136 + c16 * 8) * 2;
            const __half* src = ks[seg] + (size_t)(b*LL + kt*64 + row) * DD + h * DHD + c16 * 8;
            CP_ASYNC16(dst, src);
        }
        if (tid < 64) {
            uint32_t dst = maskB + st * 512 + tid * 8;
            const unsigned* src = &mask[(size_t)(b*LL + q0 + tid) * (LL/32) + kt*2];
            CP_ASYNC8(dst, src);
        }
        CP_COMMIT();
    };

    issue_kv(0, 0);

    const int qa_row = w * 16 + ((l >> 3) & 1) * 8 + (l & 7);
    const int qa_colB = (l >> 4) * 16;
    const int kb_rowBase = ((l >> 4) & 1) * 8 + (l & 7);
    const int kb_colB = ((l >> 3) & 1) * 16;
    const int v_row = l & 15;
    const int v_colB = (l >> 4) * 16;

    float O[16][4];
    #pragma unroll
    for (int i = 0; i < 16; i++)
        #pragma unroll
        for (int t = 0; t < 4; t++) O[i][t] = 0.f;
    float m0 = -1e30f, m1 = -1e30f, rl0 = 0.f, rl1 = 0.f;

    const int rlo2 = (w*16 + gid) * 2;
    const int rhi2 = rlo2 + 16;

    const int ktiles = qt + 1;
    for (int kt = 0; kt < ktiles; kt++) {
        const int st = kt & 1;
        if (kt + 1 < ktiles) {
            __syncthreads();
            issue_kv(kt + 1, st ^ 1);
            CP_WAIT(1);
        } else {
            CP_WAIT(0);
        }
        __syncthreads();

        const uint32_t sKH = base + (uint32_t)KVOFF(st, 0) * 2;
        const uint32_t sVH = base + (uint32_t)KVOFF(st, 1) * 2;
        const uint32_t* maskS = (const uint32_t*)(FS) + (FMASK_B >> 2) + st * 128;

        // ---- S = Qh Kh^T (1-pass) ----
        float Sc[8][4];
        #pragma unroll
        for (int i = 0; i < 8; i++)
            #pragma unroll
            for (int t = 0; t < 4; t++) Sc[i][t] = 0.f;

        #pragma unroll
        for (int kf = 0; kf < 8; kf++) {
            uint32_t aH[4];
            ldsm4(aH, base + (uint32_t)(FOFF_QH + qa_row * 136) * 2 + kf*32 + qa_colB);
            #pragma unroll
            for (int nf2 = 0; nf2 < 4; nf2++) {
                uint32_t bH[4];
                ldsm4(bH, sKH + (uint32_t)((nf2*16 + kb_rowBase) * 136) * 2 + kf*32 + kb_colB);
                mma16816(Sc[2*nf2],   aH, bH + 0);
                mma16816(Sc[2*nf2+1], aH, bH + 2);
            }
        }

        // ---- mask ----
        #pragma unroll
        for (int nf = 0; nf < 8; nf++) {
            unsigned wlo = maskS[rlo2 + (nf >> 2)];
            unsigned whi = maskS[rhi2 + (nf >> 2)];
            int sh = ((nf & 3) << 3) + (tig << 1);
            Sc[nf][0] = ((wlo >> sh) & 1u)     ? Sc[nf][0] : -1e30f;
            Sc[nf][1] = ((wlo >> (sh+1)) & 1u) ? Sc[nf][1] : -1e30f;
            Sc[nf][2] = ((whi >> sh) & 1u)     ? Sc[nf][2] : -1e30f;
            Sc[nf][3] = ((whi >> (sh+1)) & 1u) ? Sc[nf][3] : -1e30f;
        }

        // ---- online softmax ----
        float mx0 = -1e30f, mx1 = -1e30f;
        #pragma unroll
        for (int nf = 0; nf < 8; nf++) {
            mx0 = fmaxf(mx0, fmaxf(Sc[nf][0], Sc[nf][1]));
            mx1 = fmaxf(mx1, fmaxf(Sc[nf][2], Sc[nf][3]));
        }
        mx0 = fmaxf(mx0, __shfl_xor_sync(0xffffffffu, mx0, 1));
        mx0 = fmaxf(mx0, __shfl_xor_sync(0xffffffffu, mx0, 2));
        mx1 = fmaxf(mx1, __shfl_xor_sync(0xffffffffu, mx1, 1));
        mx1 = fmaxf(mx1, __shfl_xor_sync(0xffffffffu, mx1, 2));
        float nm0 = fmaxf(m0, mx0), nm1 = fmaxf(m1, mx1);
        float a0 = ex2f((m0 - nm0) * SC2), a1 = ex2f((m1 - nm1) * SC2);
        m0 = nm0; m1 = nm1;

        float s0 = 0.f, s1 = 0.f;
        #pragma unroll
        for (int nf = 0; nf < 8; nf++) {
            float p0 = ex2f((Sc[nf][0] - m0) * SC2);
            float p1 = ex2f((Sc[nf][1] - m0) * SC2);
            float p2 = ex2f((Sc[nf][2] - m1) * SC2);
            float p3 = ex2f((Sc[nf][3] - m1) * SC2);
            Sc[nf][0] = p0; Sc[nf][1] = p1; Sc[nf][2] = p2; Sc[nf][3] = p3;
            s0 += p0 + p1; s1 += p2 + p3;
        }
        s0 += __shfl_xor_sync(0xffffffffu, s0, 1);
        s0 += __shfl_xor_sync(0xffffffffu, s0, 2);
        s1 += __shfl_xor_sync(0xffffffffu, s1, 1);
        s1 += __shfl_xor_sync(0xffffffffu, s1, 2);
        rl0 = rl0 * a0 + s0;
        rl1 = rl1 * a1 + s1;

        #pragma unroll
        for (int df = 0; df < 16; df++) {
            O[df][0] *= a0; O[df][1] *= a0;
            O[df][2] *= a1; O[df][3] *= a1;
        }

        // ---- O += P V (1-pass: Ph·Vh) ----
        #pragma unroll
        for (int kf = 0; kf < 4; kf++) {
            uint32_t Pha[4];
            Pha[0] = pack_h2(Sc[2*kf][0],   Sc[2*kf][1]);
            Pha[1] = pack_h2(Sc[2*kf][2],   Sc[2*kf][3]);
            Pha[2] = pack_h2(Sc[2*kf+1][0], Sc[2*kf+1][1]);
            Pha[3] = pack_h2(Sc[2*kf+1][2], Sc[2*kf+1][3]);
            #pragma unroll
            for (int df2 = 0; df2 < 8; df2++) {
                uint32_t vh4[4];
                ldsm4t(vh4, sVH + (uint32_t)((kf*16 + v_row) * 136) * 2 + df2*32 + v_colB);
                mma16816(O[2*df2],   Pha, vh4 + 0);
                mma16816(O[2*df2+1], Pha, vh4 + 2);
            }
        }
    }

    float inv0 = 1.f / rl0, inv1 = 1.f / rl1;
    const size_t rowlo = (size_t)(b*LL + q0 + w*16 + gid) * DD + h * DHD + tig * 2;
    const size_t rowhi = rowlo + 8 * DD;
    #pragma unroll
    for (int df = 0; df < 16; df++) {
        *(uint32_t*)(Ch + rowlo + df*8) = pack_h2(O[df][0] * inv0, O[df][1] * inv0);
        *(uint32_t*)(Ch + rowhi + df*8) = pack_h2(O[df][2] * inv1, O[df][3] * inv1);
    }
}

// ================================ launch ======================================
extern "C" void kernel_launch(void* const* d_in, const int* in_sizes, int n_in,
                              void* d_out, int out_size)
{
    const float* hidden    = (const float*)d_in[0];
    const float* relevance = (const float*)d_in[1];
    const float* Wqr       = (const float*)d_in[2];
    const float* Wkr       = (const float*)d_in[3];
    const float* Wq        = (const float*)d_in[4];
    const float* Wk        = (const float*)d_in[5];
    const float* Wv        = (const float*)d_in[6];
    const float* Wo        = (const float*)d_in[7];
    float* out = (float*)d_out;

    __half *hidh,*wqh,*wkh,*wvh,*woh;
    __half *qh,*kh,*vh,*ctxh;
    __half *qrelh,*qrell,*krelh,*krell;
    float *relp,*scores; unsigned* mask;
    cudaGetSymbolAddress((void**)&hidh, g_hidh);
    cudaGetSymbolAddress((void**)&wqh,  g_wqh);
    cudaGetSymbolAddress((void**)&wkh,  g_wkh);
    cudaGetSymbolAddress((void**)&wvh,  g_wvh);
    cudaGetSymbolAddress((void**)&woh,  g_woh);
    cudaGetSymbolAddress((void**)&qh,   g_qh);
    cudaGetSymbolAddress((void**)&kh,   g_kh);
    cudaGetSymbolAddress((void**)&vh,   g_vh);
    cudaGetSymbolAddress((void**)&ctxh, g_ctxh);
    cudaGetSymbolAddress((void**)&qrelh, g_qrelh); cudaGetSymbolAddress((void**)&qrell, g_qrell);
    cudaGetSymbolAddress((void**)&krelh, g_krelh); cudaGetSymbolAddress((void**)&krell, g_krell);
    cudaGetSymbolAddress((void**)&scores, g_scores);
    cudaGetSymbolAddress((void**)&relp, g_relp); cudaGetSymbolAddress((void**)&mask, g_mask);

    cudaFuncSetAttribute(gemm_qkv, cudaFuncAttributeMaxDynamicSharedMemorySize, GSMEM);
    cudaFuncSetAttribute(gemm_o,   cudaFuncAttributeMaxDynamicSharedMemorySize, GSMEM);
    cudaFuncSetAttribute(flash_mma, cudaFuncAttributeMaxDynamicSharedMemorySize, FSMEM);
    cudaFuncSetAttribute(score_mma, cudaFuncAttributeMaxDynamicSharedMemorySize, RSMEM);

    static cudaStream_t sSide = nullptr;
    static cudaEvent_t  evFork = nullptr, evJoin = nullptr;
    if (sSide == nullptr) {
        cudaStreamCreateWithFlags(&sSide, cudaStreamNonBlocking);
        cudaEventCreateWithFlags(&evFork, cudaEventDisableTiming);
        cudaEventCreateWithFlags(&evJoin, cudaEventDisableTiming);
    }

    const int nw4 = DD * DD / 4;
    const int nAll = N4H + 3 * N4W;

    // ---- fork: relevance/mask path (+ Wo cvt) on side stream ----
    cudaEventRecord(evFork, 0);
    cudaStreamWaitEvent(sSide, evFork, 0);
    rel_proj<<<dim3(MROWS/64, 4), 256, 0, sSide>>>(relevance, Wqr, Wkr, relp);
    rel_reduce<<<(MROWS*64)/256, 256, 0, sSide>>>(relp, qrelh, qrell, krelh, krell);
    score_mma<<<dim3(16, 16, BB), 256, RSMEM, sSide>>>(qrelh, qrell, krelh, krell, scores);
    build_mask<<<dim3(LL, BB), 256, 0, sSide>>>(scores, mask);
    cvt_hi<<<(nw4 + 255)/256, 256, 0, sSide>>>((const float4*)Wo, (uint2*)woh, nw4);
    cudaEventRecord(evJoin, sSide);

    // ---- main stream: merged conversion + QKV ----
    cvt_all<<<(nAll + 255)/256, 256>>>(
        (const float4*)hidden, (const float4*)Wq, (const float4*)Wk, (const float4*)Wv,
        (uint2*)hidh, (uint2*)wqh, (uint2*)wkh, (uint2*)wvh);

    gemm_qkv<<<dim3(DD/256, MROWS/128, 3), 256, GSMEM>>>(
        hidh, wqh, qh, wkh, kh, wvh, vh);

    // ---- join, then attention + output projection ----
    cudaStreamWaitEvent(0, evJoin, 0);
    flash_mma<<<dim3(LL/64, HH, BB), 128, FSMEM>>>(qh, kh, vh, mask, ctxh);
    gemm_o<<<dim3(DD/256, MROWS/128), 256, GSMEM>>>(ctxh, woh, out);
}

// round 17
// speedup vs baseline: 1.0887x; 1.0182x over previous
#include <cuda_runtime.h>
#include <cuda_fp16.h>
#include <cstdint>
#include <math.h>

// Problem constants
#define BB   2
#define LL   2048
#define DD   2048
#define HH   16
#define DHD  128
#define DREL 64
#define KSEL 512
#define MROWS (BB*LL)   // 4096

// -------------------- scratch (device globals; no cudaMalloc allowed) ---------
__device__ __align__(256) __half g_hidh[MROWS*DD];
__device__ __align__(256) __half g_wqh [DD*DD];
__device__ __align__(256) __half g_wkh [DD*DD];
__device__ __align__(256) __half g_wvh [DD*DD];
__device__ __align__(256) __half g_woh [DD*DD];
__device__ __align__(256) __half g_qh  [MROWS*DD];
__device__ __align__(256) __half g_kh  [MROWS*DD];
__device__ __align__(256) __half g_vh  [MROWS*DD];
__device__ __align__(256) __half g_ctxh[MROWS*DD];
__device__ __align__(256) __half g_relh[MROWS*DD];
__device__ __align__(256) __half g_rell[MROWS*DD];
__device__ __align__(256) __half g_wqrh[DREL*DD];
__device__ __align__(256) __half g_wqrl[DREL*DD];
__device__ __align__(256) __half g_wkrh[DREL*DD];
__device__ __align__(256) __half g_wkrl[DREL*DD];
__device__ __align__(256) __half g_qrelh[MROWS*DREL];
__device__ __align__(256) __half g_qrell[MROWS*DREL];
__device__ __align__(256) __half g_krelh[MROWS*DREL];
__device__ __align__(256) __half g_krell[MROWS*DREL];
__device__ __align__(256) float    g_scores[(size_t)BB*LL*LL];
__device__ __align__(256) float    g_relp[4*MROWS*128];
__device__ __align__(256) unsigned g_mask[BB*LL*(LL/32)];

// ========================= inline PTX helpers =================================
__device__ __forceinline__ uint32_t smem_u32(const void* p) {
    uint32_t a;
    asm("{ .reg .u64 t; cvta.to.shared.u64 t, %1; cvt.u32.u64 %0, t; }" : "=r"(a) : "l"(p));
    return a;
}
__device__ __forceinline__ void ldsm4(uint32_t* r, uint32_t addr) {
    asm volatile("ldmatrix.sync.aligned.m8n8.x4.shared.b16 {%0,%1,%2,%3}, [%4];"
        : "=r"(r[0]), "=r"(r[1]), "=r"(r[2]), "=r"(r[3]) : "r"(addr));
}
__device__ __forceinline__ void ldsm4t(uint32_t* r, uint32_t addr) {
    asm volatile("ldmatrix.sync.aligned.m8n8.x4.trans.shared.b16 {%0,%1,%2,%3}, [%4];"
        : "=r"(r[0]), "=r"(r[1]), "=r"(r[2]), "=r"(r[3]) : "r"(addr));
}
__device__ __forceinline__ void mma16816(float* c, const uint32_t* a, const uint32_t* b) {
    asm volatile("mma.sync.aligned.m16n8k16.row.col.f32.f16.f16.f32 "
        "{%0,%1,%2,%3}, {%4,%5,%6,%7}, {%8,%9}, {%0,%1,%2,%3};"
        : "+f"(c[0]), "+f"(c[1]), "+f"(c[2]), "+f"(c[3])
        : "r"(a[0]), "r"(a[1]), "r"(a[2]), "r"(a[3]), "r"(b[0]), "r"(b[1]));
}
#define CP_ASYNC16(dst, src) \
    asm volatile("cp.async.cg.shared.global [%0], [%1], 16;" :: "r"(dst), "l"(src) : "memory")
#define CP_ASYNC8(dst, src) \
    asm volatile("cp.async.ca.shared.global [%0], [%1], 8;" :: "r"(dst), "l"(src) : "memory")
#define CP_COMMIT() asm volatile("cp.async.commit_group;" ::: "memory")
#define CP_WAIT(n)  asm volatile("cp.async.wait_group %0;" :: "n"(n) : "memory")

__device__ __forceinline__ float ex2f(float x) {
    float y; asm("ex2.approx.f32 %0, %1;" : "=f"(y) : "f"(x)); return y;
}
__device__ __forceinline__ uint32_t pack_h2(float x, float y) {
    __half hx = __float2half_rn(x), hy = __float2half_rn(y);
    return ((uint32_t)__half_as_ushort(hy) << 16) | __half_as_ushort(hx);
}
__device__ __forceinline__ void split2(float x, float y, uint32_t& hi, uint32_t& lo) {
    __half hx = __float2half_rn(x), hy = __float2half_rn(y);
    __half lx = __float2half_rn(x - __half2float(hx));
    __half ly = __float2half_rn(y - __half2float(hy));
    hi = ((uint32_t)__half_as_ushort(hy) << 16) | __half_as_ushort(hx);
    lo = ((uint32_t)__half_as_ushort(ly) << 16) | __half_as_ushort(lx);
}

// =========================== fp32 -> fp16 conversions =========================
__global__ __launch_bounds__(256) void cvt_hi(
    const float4* __restrict__ x, uint2* __restrict__ h, int n4)
{
    int i = blockIdx.x * 256 + threadIdx.x;
    if (i >= n4) return;
    float4 v = x[i];
    h[i] = make_uint2(pack_h2(v.x, v.y), pack_h2(v.z, v.w));
}

#define N4H (MROWS*DD/4)
#define N4W (DD*DD/4)
__global__ __launch_bounds__(256) void cvt_all(
    const float4* __restrict__ hid, const float4* __restrict__ w0,
    const float4* __restrict__ w1,  const float4* __restrict__ w2,
    uint2* __restrict__ hh, uint2* __restrict__ h0,
    uint2* __restrict__ h1, uint2* __restrict__ h2)
{
    int i = blockIdx.x * 256 + threadIdx.x;
    const float4* src; uint2* dst; int off;
    if (i < N4H)                { src = hid; dst = hh; off = i; }
    else if (i < N4H + N4W)     { src = w0;  dst = h0; off = i - N4H; }
    else if (i < N4H + 2*N4W)   { src = w1;  dst = h1; off = i - N4H - N4W; }
    else if (i < N4H + 3*N4W)   { src = w2;  dst = h2; off = i - N4H - 2*N4W; }
    else return;
    float4 v = src[off];
    dst[off] = make_uint2(pack_h2(v.x, v.y), pack_h2(v.z, v.w));
}

// relevance + Wqr + Wkr -> hi/lo split (flattened)
#define N4WR (DREL*DD/4)
__global__ __launch_bounds__(256) void cvt_rel(
    const float4* __restrict__ rel, const float4* __restrict__ wqr,
    const float4* __restrict__ wkr,
    uint2* __restrict__ rh, uint2* __restrict__ rl,
    uint2* __restrict__ qh, uint2* __restrict__ ql,
    uint2* __restrict__ kh, uint2* __restrict__ kl)
{
    int i = blockIdx.x * 256 + threadIdx.x;
    const float4* src; uint2 *dh, *dl; int off;
    if (i < N4H)                 { src = rel; dh = rh; dl = rl; off = i; }
    else if (i < N4H + N4WR)     { src = wqr; dh = qh; dl = ql; off = i - N4H; }
    else if (i < N4H + 2*N4WR)   { src = wkr; dh = kh; dl = kl; off = i - N4H - N4WR; }
    else return;
    float4 v = src[off];
    uint32_t h0, l0, h1, l1;
    split2(v.x, v.y, h0, l0);
    split2(v.z, v.w, h1, l1);
    dh[off] = make_uint2(h0, h1);
    dl[off] = make_uint2(l0, l1);
}

// ===== fp16 GEMM: C = Ah · Bh^T (1-pass) ======================================
// CTA tile 128x256, warp tile 64x64 (8 warps), k-chunk 64, 3-stage cp.async.
#define GROWB 144
#define SEGA64 (128*GROWB)       // 18432
#define SEGB64 (256*GROWB)       // 36864
#define STAGE64 (SEGA64+SEGB64)  // 55296
#define GSMEM (3*STAGE64)        // 165888

template<int OUTMODE>
__device__ __forceinline__ void gemm_body(
    const __half* __restrict__ Ah, const __half* __restrict__ Bh,
    float* __restrict__ Cf, __half* __restrict__ Ch,
    __half* GS)
{
    const uint32_t base = smem_u32(GS);
    const int tid = threadIdx.x;
    const int l   = tid & 31;
    const int wid = tid >> 5;
    const int wm  = wid >> 2;
    const int wn  = wid & 3;
    const int bm  = blockIdx.y * 128;
    const int bn  = blockIdx.x * 256;

    const __half* Ah_p = Ah + (size_t)bm * DD;
    const __half* Bh_p = Bh + (size_t)bn * DD;

    const int rA = wm * 64 + ((l >> 3) & 1) * 8 + (l & 7);
    const int kA = (l >> 4) * 16;
    const int rB = wn * 64 + ((l >> 4) & 1) * 8 + (l & 7);
    const int kB = ((l >> 3) & 1) * 16;

    float acc[4][8][4];
    #pragma unroll
    for (int i = 0; i < 4; i++)
        #pragma unroll
        for (int j = 0; j < 8; j++)
            #pragma unroll
            for (int t = 0; t < 4; t++) acc[i][j][t] = 0.f;

    auto issue_stage = [&](int c, int st) {
        const uint32_t stb = base + (uint32_t)st * STAGE64;
        #pragma unroll
        for (int j = 0; j < 12; j++) {
            int idx = tid + j * 256;
            uint32_t dst; const __half* src;
            if (j < 4) {
                int row = idx >> 3, c16 = idx & 7;
                dst = stb + (uint32_t)row * GROWB + c16 * 16;
                src = Ah_p + (size_t)row * DD + c * 64 + c16 * 8;
            } else {
                int rem = idx - 1024;
                int row = rem >> 3, c16 = rem & 7;
                dst = stb + SEGA64 + (uint32_t)row * GROWB + c16 * 16;
                src = Bh_p + (size_t)row * DD + c * 64 + c16 * 8;
            }
            CP_ASYNC16(dst, src);
        }
        CP_COMMIT();
    };

    issue_stage(0, 0);
    issue_stage(1, 1);

    for (int c = 0; c < DD / 64; c++) {
        CP_WAIT(1);
        __syncthreads();
        if (c + 2 < DD / 64) issue_stage(c + 2, (c + 2) % 3);
        else CP_COMMIT();

        const int st = c % 3;
        const uint32_t sAh = base + (uint32_t)st * STAGE64;
        const uint32_t sBh = sAh + SEGA64;

        #pragma unroll
        for (int ks = 0; ks < 4; ks++) {
            uint32_t aH[4][4];
            #pragma unroll
            for (int mf = 0; mf < 4; mf++)
                ldsm4(aH[mf], sAh + (uint32_t)(rA + mf*16) * GROWB + kA + ks*32);
            #pragma unroll
            for (int nf4 = 0; nf4 < 4; nf4++) {
                uint32_t bH[4];
                ldsm4(bH, sBh + (uint32_t)(rB + nf4*16) * GROWB + kB + ks*32);
                #pragma unroll
                for (int mf = 0; mf < 4; mf++) {
                    mma16816(acc[mf][2*nf4],   aH[mf], bH + 0);
                    mma16816(acc[mf][2*nf4+1], aH[mf], bH + 2);
                }
            }
        }
    }

    const int gid = l >> 2, tig = l & 3;
    #pragma unroll
    for (int mf = 0; mf < 4; mf++) {
        #pragma unroll
        for (int nf = 0; nf < 8; nf++) {
            int r0 = bm + wm*64 + mf*16 + gid;
            int cc = bn + wn*64 + nf*8 + tig*2;
            if (OUTMODE == 2) {
                *(float2*)(Cf + (size_t)r0 * DD + cc)       = make_float2(acc[mf][nf][0], acc[mf][nf][1]);
                *(float2*)(Cf + (size_t)(r0 + 8) * DD + cc) = make_float2(acc[mf][nf][2], acc[mf][nf][3]);
            } else {
                *(uint32_t*)(Ch + (size_t)r0 * DD + cc)       = pack_h2(acc[mf][nf][0], acc[mf][nf][1]);
                *(uint32_t*)(Ch + (size_t)(r0 + 8) * DD + cc) = pack_h2(acc[mf][nf][2], acc[mf][nf][3]);
            }
        }
    }
}

__global__ __launch_bounds__(256) void gemm_qkv(
    const __half* __restrict__ Ah,
    const __half* __restrict__ Wqh, __half* __restrict__ Qh,
    const __half* __restrict__ Wkh, __half* __restrict__ Kh,
    const __half* __restrict__ Wvh, __half* __restrict__ Vh)
{
    extern __shared__ __half GS[];
    if (blockIdx.z == 0)
        gemm_body<1>(Ah, Wqh, nullptr, Qh, GS);
    else if (blockIdx.z == 1)
        gemm_body<1>(Ah, Wkh, nullptr, Kh, GS);
    else
        gemm_body<1>(Ah, Wvh, nullptr, Vh, GS);
}

__global__ __launch_bounds__(256) void gemm_o(
    const __half* __restrict__ Ah,
    const __half* __restrict__ Bh, float* __restrict__ Cf)
{
    extern __shared__ __half GS[];
    gemm_body<2>(Ah, Bh, Cf, nullptr, GS);
}

// ===== rel projection GEMM (3-pass fp16-split, split-K 4, fp32 partials) ======
// part[ks][4096][128]: cols 0-63 = qrel, 64-127 = krel.
// CTA tile 128x128, warp 64x32 (8 warps), k-chunk 64, double-buffered.
#define RMSEG  (128*GROWB)            // 18432 per segment
#define RMSTG  (4*RMSEG)              // Ah, Al, Bh, Bl  = 73728
#define RMSMEM (2*RMSTG)              // 147456

__global__ __launch_bounds__(256) void rel_mma(
    const __half* __restrict__ Rh, const __half* __restrict__ Rl,
    const __half* __restrict__ Wqrh, const __half* __restrict__ Wqrl,
    const __half* __restrict__ Wkrh, const __half* __restrict__ Wkrl,
    float* __restrict__ part)
{
    extern __shared__ __half RMS[];
    const uint32_t base = smem_u32(RMS);
    const int tid = threadIdx.x;
    const int l = tid & 31, wid = tid >> 5;
    const int wm = wid >> 2, wn = wid & 3;
    const int m0 = blockIdx.y * 128;
    const int kb = blockIdx.x * 512;

    const __half* Ah_p = Rh + (size_t)m0 * DD + kb;
    const __half* Al_p = Rl + (size_t)m0 * DD + kb;

    auto issue_stage = [&](int c, int st) {
        const uint32_t stb = base + (uint32_t)st * RMSTG;
        #pragma unroll
        for (int j = 0; j < 16; j++) {          // 4096 16B chunks
            int idx = tid + j * 256;
            int seg = idx >> 10, rem = idx & 1023;
            int row = rem >> 3, c16 = rem & 7;
            uint32_t dst = stb + (uint32_t)seg * RMSEG + (uint32_t)row * GROWB + c16 * 16;
            const __half* src;
            if (seg == 0)      src = Ah_p + (size_t)row * DD + c * 64 + c16 * 8;
            else if (seg == 1) src = Al_p + (size_t)row * DD + c * 64 + c16 * 8;
            else {
                const __half* wb = (seg == 2)
                    ? ((row < 64) ? Wqrh + (size_t)row * DD : Wkrh + (size_t)(row - 64) * DD)
                    : ((row < 64) ? Wqrl + (size_t)row * DD : Wkrl + (size_t)(row - 64) * DD);
                src = wb + kb + c * 64 + c16 * 8;
            }
            CP_ASYNC16(dst, src);
        }
        CP_COMMIT();
    };

    const int rA = wm * 64 + ((l >> 3) & 1) * 8 + (l & 7);
    const int kA = (l >> 4) * 16;
    const int rB = wn * 32 + ((l >> 4) & 1) * 8 + (l & 7);
    const int kB = ((l >> 3) & 1) * 16;

    float acc[4][4][4];
    #pragma unroll
    for (int a = 0; a < 4; a++)
        #pragma unroll
        for (int c = 0; c < 4; c++)
            #pragma unroll
            for (int t = 0; t < 4; t++) acc[a][c][t] = 0.f;

    issue_stage(0, 0);
    issue_stage(1, 1);

    for (int c = 0; c < 8; c++) {               // 512 / 64
        CP_WAIT(1);
        __syncthreads();

        const uint32_t stb = base + (uint32_t)(c & 1) * RMSTG;
        const uint32_t sAh = stb, sAl = stb + RMSEG;
        const uint32_t sBh = stb + 2*RMSEG, sBl = stb + 3*RMSEG;

        #pragma unroll
        for (int ks = 0; ks < 4; ks++) {
            uint32_t aH[4][4], aL[4][4];
            #pragma unroll
            for (int mf = 0; mf < 4; mf++) {
                ldsm4(aH[mf], sAh + (uint32_t)(rA + mf*16) * GROWB + kA + ks*32);
                ldsm4(aL[mf], sAl + (uint32_t)(rA + mf*16) * GROWB + kA + ks*32);
            }
            #pragma unroll
            for (int nf2 = 0; nf2 < 2; nf2++) {
                uint32_t bH[4], bL[4];
                ldsm4(bH, sBh + (uint32_t)(rB + nf2*16) * GROWB + kB + ks*32);
                #pragma unroll
                for (int mf = 0; mf < 4; mf++) {
                    mma16816(acc[mf][2*nf2],   aH[mf], bH + 0);
                    mma16816(acc[mf][2*nf2+1], aH[mf], bH + 2);
                    mma16816(acc[mf][2*nf2],   aL[mf], bH + 0);
                    mma16816(acc[mf][2*nf2+1], aL[mf], bH + 2);
                }
                ldsm4(bL, sBl + (uint32_t)(rB + nf2*16) * GROWB + kB + ks*32);
                #pragma unroll
                for (int mf = 0; mf < 4; mf++) {
                    mma16816(acc[mf][2*nf2],   aH[mf], bL + 0);
                    mma16816(acc[mf][2*nf2+1], aH[mf], bL + 2);
                }
            }
        }
        __syncthreads();                        // done reading buf c&1
        if (c + 2 < 8) issue_stage(c + 2, c & 1);
    }

    float* dst = part + (size_t)blockIdx.x * MROWS * 128;
    const int gid = l >> 2, tig = l & 3;
    #pragma unroll
    for (int mf = 0; mf < 4; mf++) {
        #pragma unroll
        for (int nf = 0; nf < 4; nf++) {
            int r0 = m0 + wm*64 + mf*16 + gid;
            int cc = wn*32 + nf*8 + tig*2;
            *(float2*)(dst + (size_t)r0 * 128 + cc)       = make_float2(acc[mf][nf][0], acc[mf][nf][1]);
            *(float2*)(dst + (size_t)(r0 + 8) * 128 + cc) = make_float2(acc[mf][nf][2], acc[mf][nf][3]);
        }
    }
}

__global__ __launch_bounds__(256) void rel_reduce(
    const float* __restrict__ part,
    __half* __restrict__ qh, __half* __restrict__ ql,
    __half* __restrict__ kh, __half* __restrict__ kl)
{
    int idx = blockIdx.x * 256 + threadIdx.x;
    int row = idx >> 6, col = idx & 63;
    float sq = 0.f, sk = 0.f;
    #pragma unroll
    for (int s = 0; s < 4; s++) {
        const float* p = part + (size_t)s * MROWS * 128 + (size_t)row * 128;
        sq += p[col]; sk += p[col + 64];
    }
    __half hq = __float2half_rn(sq);
    __half hk = __float2half_rn(sk);
    qh[(size_t)row * 64 + col] = hq;
    ql[(size_t)row * 64 + col] = __float2half_rn(sq - __half2float(hq));
    kh[(size_t)row * 64 + col] = hk;
    kl[(size_t)row * 64 + col] = __float2half_rn(sk - __half2float(hk));
}

// ======== rel score GEMM: S[b] = qrel · krel^T (3-pass fp16 split, fp32 out) ==
#define RSTRIDE 144
#define RSEGB (128*RSTRIDE)
#define RSMEM (4*RSEGB)

__global__ __launch_bounds__(256) void score_mma(
    const __half* __restrict__ Qrh, const __half* __restrict__ Qrl,
    const __half* __restrict__ Krh, const __half* __restrict__ Krl,
    float* __restrict__ scores)
{
    const int j = blockIdx.x, i = blockIdx.y, b = blockIdx.z;
    if (j > i) return;
    extern __shared__ __half RS[];
    const uint32_t base = smem_u32(RS);
    const int tid = threadIdx.x;
    const int l = tid & 31, wid = tid >> 5;
    const int wm = wid >> 2, wn = wid & 3;
    const int q0 = i * 128, k0 = j * 128;

    const __half* srcs[4] = {
        Qrh + (size_t)(b*LL + q0) * DREL, Qrl + (size_t)(b*LL + q0) * DREL,
        Krh + (size_t)(b*LL + k0) * DREL, Krl + (size_t)(b*LL + k0) * DREL};

    #pragma unroll
    for (int jj = 0; jj < 16; jj++) {
        int idx = tid + jj * 256;
        int seg = idx >> 10, rem = idx & 1023;
        int row = rem >> 3, c16 = rem & 7;
        uint32_t dst = base + (uint32_t)seg * RSEGB + (uint32_t)row * RSTRIDE + c16 * 16;
        const __half* src = srcs[seg] + (size_t)row * DREL + c16 * 8;
        CP_ASYNC16(dst, src);
    }
    CP_COMMIT();
    CP_WAIT(0);
    __syncthreads();

    const int rA = wm * 64 + ((l >> 3) & 1) * 8 + (l & 7);
    const int kA = (l >> 4) * 16;
    const int rB = wn * 32 + ((l >> 4) & 1) * 8 + (l & 7);
    const int kB = ((l >> 3) & 1) * 16;
    const uint32_t sQh = base, sQl = base + RSEGB;
    const uint32_t sKh = base + 2*RSEGB, sKl = base + 3*RSEGB;

    float acc[4][4][4];
    #pragma unroll
    for (int a = 0; a < 4; a++)
        #pragma unroll
        for (int c = 0; c < 4; c++)
            #pragma unroll
            for (int t = 0; t < 4; t++) acc[a][c][t] = 0.f;

    #pragma unroll
    for (int ks = 0; ks < 4; ks++) {
        uint32_t aH[4][4], aL[4][4];
        #pragma unroll
        for (int mf = 0; mf < 4; mf++) {
            ldsm4(aH[mf], sQh + (uint32_t)(rA + mf*16) * RSTRIDE + kA + ks*32);
            ldsm4(aL[mf], sQl + (uint32_t)(rA + mf*16) * RSTRIDE + kA + ks*32);
        }
        #pragma unroll
        for (int nf2 = 0; nf2 < 2; nf2++) {
            uint32_t bH[4], bL[4];
            ldsm4(bH, sKh + (uint32_t)(rB + nf2*16) * RSTRIDE + kB + ks*32);
            #pragma unroll
            for (int mf = 0; mf < 4; mf++) {
                mma16816(acc[mf][2*nf2],   aH[mf], bH + 0);
                mma16816(acc[mf][2*nf2+1], aH[mf], bH + 2);
                mma16816(acc[mf][2*nf2],   aL[mf], bH + 0);
                mma16816(acc[mf][2*nf2+1], aL[mf], bH + 2);
            }
            ldsm4(bL, sKl + (uint32_t)(rB + nf2*16) * RSTRIDE + kB + ks*32);
            #pragma unroll
            for (int mf = 0; mf < 4; mf++) {
                mma16816(acc[mf][2*nf2],   aH[mf], bL + 0);
                mma16816(acc[mf][2*nf2+1], aH[mf], bL + 2);
            }
        }
    }

    const int gid = l >> 2, tig = l & 3;
    #pragma unroll
    for (int mf = 0; mf < 4; mf++) {
        #pragma unroll
        for (int nf = 0; nf < 4; nf++) {
            int r0 = q0 + wm*64 + mf*16 + gid;
            int cc = k0 + wn*32 + nf*8 + tig*2;
            float* s0p = scores + ((size_t)(b*LL) + r0) * LL + cc;
            *(float2*)s0p            = make_float2(acc[mf][nf][0], acc[mf][nf][1]);
            *(float2*)(s0p + 8 * LL) = make_float2(acc[mf][nf][2], acc[mf][nf][3]);
        }
    }
}

// ====================== top-K mask build (one block per (b,q)) ================
__device__ __forceinline__ unsigned ford(float f) {
    unsigned u = __float_as_uint(f);
    return (u & 0x80000000u) ? ~u : (u | 0x80000000u);
}

__global__ __launch_bounds__(256) void build_mask(
    const float* __restrict__ scores, unsigned* __restrict__ mask)
{
    const int q = blockIdx.x;
    const int b = blockIdx.y;
    const int tid = threadIdx.x;

    __shared__ float    s[LL];
    __shared__ unsigned mw[LL/32];
    __shared__ int      hist[256];
    __shared__ int      scan[256];
    __shared__ unsigned sh_prefix;
    __shared__ int      sh_R;

    if (tid < LL/32) mw[tid] = 0u;
    const int n = q + 1;

    if (n <= KSEL) {
        __syncthreads();
        for (int k = tid; k < n; k += 256)
            atomicOr(&mw[k>>5], 1u << (k & 31));
    } else {
        const float* srow = scores + ((size_t)(b*LL + q)) * LL;
        for (int k = tid; k < n; k += 256) s[k] = srow[k];
        __syncthreads();

        unsigned prefix = 0u; int R = KSEL;
        for (int byte = 3; byte >= 0; byte--) {
            hist[tid] = 0;
            __syncthreads();
            const int shift = byte * 8;
            const unsigned pm = (byte == 3) ? 0u : (0xFFFFFFFFu << (shift + 8));
            for (int k = tid; k < n; k += 256) {
                unsigned u = ford(s[k]);
                if ((u & pm) == (prefix & pm))
                    atomicAdd(&hist[(u >> shift) & 255], 1);
            }
            __syncthreads();
            int hv = hist[tid];
            scan[tid] = hv;
            __syncthreads();
            #pragma unroll
            for (int off = 1; off < 256; off <<= 1) {
                int t = (tid + off < 256) ? scan[tid + off] : 0;
                __syncthreads();
                scan[tid] += t;
                __syncthreads();
            }
            int inc = scan[tid];
            int above = inc - hv;
            if (above < R && inc >= R) {
                sh_prefix = prefix | ((unsigned)tid << shift);
                sh_R = R - above;
            }
            __syncthreads();
            prefix = sh_prefix; R = sh_R;
            __syncthreads();
        }
        const unsigned T = prefix;
        for (int k = tid; k < n; k += 256)
            if (ford(s[k]) > T) atomicOr(&mw[k>>5], 1u << (k & 31));
        const int per = (n + 255) >> 8;
        const int lo = tid * per;
        const int hi = (lo + per < n) ? lo + per : n;
        int cnt = 0;
        for (int k = lo; k < hi; k++)
            if (ford(s[k]) == T) cnt++;
        scan[tid] = cnt;
        __syncthreads();
        #pragma unroll
        for (int off = 1; off < 256; off <<= 1) {
            int t = (tid >= off) ? scan[tid - off] : 0;
            __syncthreads();
            scan[tid] += t;
            __syncthreads();
        }
        int excl = scan[tid] - cnt;
        int r2 = R - excl;
        if (r2 > 0) {
            for (int k = lo; k < hi && r2 > 0; k++)
                if (ford(s[k]) == T) { atomicOr(&mw[k>>5], 1u << (k & 31)); r2--; }
        }
    }
    __syncthreads();
    if (tid == 0) mw[q>>5] |= 1u << (q & 31);
    __syncthreads();
    if (tid < LL/32) mask[(size_t)(b*LL + q)*(LL/32) + tid] = mw[tid];
}

// ====================== flash attention (fp16 mma) ============================
// 4 warps, Q-tile 64 (hi), K/V 64 (hi), QK 1-pass, PV 1-pass,
// double-buffered KV, 2 CTAs/SM (cross-CTA phase overlap).
#define QSEG 8704       // 64*136 halves
#define KSEG 8704
#define FOFF_QH 0
#define KVOFF(st, seg) (QSEG + (st)*2*KSEG + (seg)*KSEG)
#define FMASK_B ((QSEG + 4*KSEG)*2)
#define FSMEM   (FMASK_B + 2*512)
#define SC2 0.12751744416168355f               // (1/sqrt(128)) * log2(e)

__global__ __launch_bounds__(128) void flash_mma(
    const __half* __restrict__ Qh,
    const __half* __restrict__ Kh, const __half* __restrict__ Vh,
    const unsigned* __restrict__ mask,
    __half* __restrict__ Ch)
{
    extern __shared__ __half FS[];
    const uint32_t base = smem_u32(FS);
    const uint32_t maskB = base + FMASK_B;

    const int qt = (int)gridDim.x - 1 - (int)blockIdx.x;   // heavy tiles first
    const int h = blockIdx.y, b = blockIdx.z;
    const int q0 = qt * 64;
    const int tid = threadIdx.x;
    const int w = tid >> 5, l = tid & 31;
    const int gid = l >> 2, tig = l & 3;

    // Q load (one-time)
    {
        #pragma unroll
        for (int j = 0; j < 8; j++) {
            int idx = tid + j * 128;
            int row = idx >> 4, c16 = idx & 15;
            uint32_t dst = base + (uint32_t)(row * 136 + c16 * 8) * 2;
            const __half* src = Qh + (size_t)(b*LL + q0 + row) * DD + h * DHD + c16 * 8;
            CP_ASYNC16(dst, src);
        }
        CP_COMMIT();
    }

    auto issue_kv = [&](int kt, int st) {
        const __half* ks[2] = {Kh, Vh};
        #pragma unroll
        for (int j = 0; j < 16; j++) {
            int idx = tid + j * 128;
            int seg = idx >> 10, rem = idx & 1023;
            int row = rem >> 4, c16 = rem & 15;
            uint32_t dst = base + (uint32_t)(KVOFF(st, seg) + row * 136 + c16 * 8) * 2;
            const __half* src = ks[seg] + (size_t)(b*LL + kt*64 + row) * DD + h * DHD + c16 * 8;
            CP_ASYNC16(dst, src);
        }
        if (tid < 64) {
            uint32_t dst = maskB + st * 512 + tid * 8;
            const unsigned* src = &mask[(size_t)(b*LL + q0 + tid) * (LL/32) + kt*2];
            CP_ASYNC8(dst, src);
        }
        CP_COMMIT();
    };

    issue_kv(0, 0);

    const int qa_row = w * 16 + ((l >> 3) & 1) * 8 + (l & 7);
    const int qa_colB = (l >> 4) * 16;
    const int kb_rowBase = ((l >> 4) & 1) * 8 + (l & 7);
    const int kb_colB = ((l >> 3) & 1) * 16;
    const int v_row = l & 15;
    const int v_colB = (l >> 4) * 16;

    float O[16][4];
    #pragma unroll
    for (int i = 0; i < 16; i++)
        #pragma unroll
        for (int t = 0; t < 4; t++) O[i][t] = 0.f;
    float m0 = -1e30f, m1 = -1e30f, rl0 = 0.f, rl1 = 0.f;

    const int rlo2 = (w*16 + gid) * 2;
    const int rhi2 = rlo2 + 16;

    const int ktiles = qt + 1;
    for (int kt = 0; kt < ktiles; kt++) {
        const int st = kt & 1;
        if (kt + 1 < ktiles) {
            __syncthreads();
            issue_kv(kt + 1, st ^ 1);
            CP_WAIT(1);
        } else {
            CP_WAIT(0);
        }
        __syncthreads();

        const uint32_t sKH = base + (uint32_t)KVOFF(st, 0) * 2;
        const uint32_t sVH = base + (uint32_t)KVOFF(st, 1) * 2;
        const uint32_t* maskS = (const uint32_t*)(FS) + (FMASK_B >> 2) + st * 128;

        // ---- S = Qh Kh^T (1-pass) ----
        float Sc[8][4];
        #pragma unroll
        for (int i = 0; i < 8; i++)
            #pragma unroll
            for (int t = 0; t < 4; t++) Sc[i][t] = 0.f;

        #pragma unroll
        for (int kf = 0; kf < 8; kf++) {
            uint32_t aH[4];
            ldsm4(aH, base + (uint32_t)(FOFF_QH + qa_row * 136) * 2 + kf*32 + qa_colB);
            #pragma unroll
            for (int nf2 = 0; nf2 < 4; nf2++) {
                uint32_t bH[4];
                ldsm4(bH, sKH + (uint32_t)((nf2*16 + kb_rowBase) * 136) * 2 + kf*32 + kb_colB);
                mma16816(Sc[2*nf2],   aH, bH + 0);
                mma16816(Sc[2*nf2+1], aH, bH + 2);
            }
        }

        // ---- mask ----
        #pragma unroll
        for (int nf = 0; nf < 8; nf++) {
            unsigned wlo = maskS[rlo2 + (nf >> 2)];
            unsigned whi = maskS[rhi2 + (nf >> 2)];
            int sh = ((nf & 3) << 3) + (tig << 1);
            Sc[nf][0] = ((wlo >> sh) & 1u)     ? Sc[nf][0] : -1e30f;
            Sc[nf][1] = ((wlo >> (sh+1)) & 1u) ? Sc[nf][1] : -1e30f;
            Sc[nf][2] = ((whi >> sh) & 1u)     ? Sc[nf][2] : -1e30f;
            Sc[nf][3] = ((whi >> (sh+1)) & 1u) ? Sc[nf][3] : -1e30f;
        }

        // ---- online softmax ----
        float mx0 = -1e30f, mx1 = -1e30f;
        #pragma unroll
        for (int nf = 0; nf < 8; nf++) {
            mx0 = fmaxf(mx0, fmaxf(Sc[nf][0], Sc[nf][1]));
            mx1 = fmaxf(mx1, fmaxf(Sc[nf][2], Sc[nf][3]));
        }
        mx0 = fmaxf(mx0, __shfl_xor_sync(0xffffffffu, mx0, 1));
        mx0 = fmaxf(mx0, __shfl_xor_sync(0xffffffffu, mx0, 2));
        mx1 = fmaxf(mx1, __shfl_xor_sync(0xffffffffu, mx1, 1));
        mx1 = fmaxf(mx1, __shfl_xor_sync(0xffffffffu, mx1, 2));
        float nm0 = fmaxf(m0, mx0), nm1 = fmaxf(m1, mx1);
        float a0 = ex2f((m0 - nm0) * SC2), a1 = ex2f((m1 - nm1) * SC2);
        m0 = nm0; m1 = nm1;

        float s0 = 0.f, s1 = 0.f;
        #pragma unroll
        for (int nf = 0; nf < 8; nf++) {
            float p0 = ex2f((Sc[nf][0] - m0) * SC2);
            float p1 = ex2f((Sc[nf][1] - m0) * SC2);
            float p2 = ex2f((Sc[nf][2] - m1) * SC2);
            float p3 = ex2f((Sc[nf][3] - m1) * SC2);
            Sc[nf][0] = p0; Sc[nf][1] = p1; Sc[nf][2] = p2; Sc[nf][3] = p3;
            s0 += p0 + p1; s1 += p2 + p3;
        }
        s0 += __shfl_xor_sync(0xffffffffu, s0, 1);
        s0 += __shfl_xor_sync(0xffffffffu, s0, 2);
        s1 += __shfl_xor_sync(0xffffffffu, s1, 1);
        s1 += __shfl_xor_sync(0xffffffffu, s1, 2);
        rl0 = rl0 * a0 + s0;
        rl1 = rl1 * a1 + s1;

        #pragma unroll
        for (int df = 0; df < 16; df++) {
            O[df][0] *= a0; O[df][1] *= a0;
            O[df][2] *= a1; O[df][3] *= a1;
        }

        // ---- O += P V (1-pass: Ph·Vh) ----
        #pragma unroll
        for (int kf = 0; kf < 4; kf++) {
            uint32_t Pha[4];
            Pha[0] = pack_h2(Sc[2*kf][0],   Sc[2*kf][1]);
            Pha[1] = pack_h2(Sc[2*kf][2],   Sc[2*kf][3]);
            Pha[2] = pack_h2(Sc[2*kf+1][0], Sc[2*kf+1][1]);
            Pha[3] = pack_h2(Sc[2*kf+1][2], Sc[2*kf+1][3]);
            #pragma unroll
            for (int df2 = 0; df2 < 8; df2++) {
                uint32_t vh4[4];
                ldsm4t(vh4, sVH + (uint32_t)((kf*16 + v_row) * 136) * 2 + df2*32 + v_colB);
                mma16816(O[2*df2],   Pha, vh4 + 0);
                mma16816(O[2*df2+1], Pha, vh4 + 2);
            }
        }
    }

    float inv0 = 1.f / rl0, inv1 = 1.f / rl1;
    const size_t rowlo = (size_t)(b*LL + q0 + w*16 + gid) * DD + h * DHD + tig * 2;
    const size_t rowhi = rowlo + 8 * DD;
    #pragma unroll
    for (int df = 0; df < 16; df++) {
        *(uint32_t*)(Ch + rowlo + df*8) = pack_h2(O[df][0] * inv0, O[df][1] * inv0);
        *(uint32_t*)(Ch + rowhi + df*8) = pack_h2(O[df][2] * inv1, O[df][3] * inv1);
    }
}

// ================================ launch ======================================
extern "C" void kernel_launch(void* const* d_in, const int* in_sizes, int n_in,
                              void* d_out, int out_size)
{
    const float* hidden    = (const float*)d_in[0];
    const float* relevance = (const float*)d_in[1];
    const float* Wqr       = (const float*)d_in[2];
    const float* Wkr       = (const float*)d_in[3];
    const float* Wq        = (const float*)d_in[4];
    const float* Wk        = (const float*)d_in[5];
    const float* Wv        = (const float*)d_in[6];
    const float* Wo        = (const float*)d_in[7];
    float* out = (float*)d_out;

    __half *hidh,*wqh,*wkh,*wvh,*woh;
    __half *qh,*kh,*vh,*ctxh;
    __half *relh,*rell,*wqrh,*wqrl,*wkrh,*wkrl;
    __half *qrelh,*qrell,*krelh,*krell;
    float *relp,*scores; unsigned* mask;
    cudaGetSymbolAddress((void**)&hidh, g_hidh);
    cudaGetSymbolAddress((void**)&wqh,  g_wqh);
    cudaGetSymbolAddress((void**)&wkh,  g_wkh);
    cudaGetSymbolAddress((void**)&wvh,  g_wvh);
    cudaGetSymbolAddress((void**)&woh,  g_woh);
    cudaGetSymbolAddress((void**)&qh,   g_qh);
    cudaGetSymbolAddress((void**)&kh,   g_kh);
    cudaGetSymbolAddress((void**)&vh,   g_vh);
    cudaGetSymbolAddress((void**)&ctxh, g_ctxh);
    cudaGetSymbolAddress((void**)&relh, g_relh); cudaGetSymbolAddress((void**)&rell, g_rell);
    cudaGetSymbolAddress((void**)&wqrh, g_wqrh); cudaGetSymbolAddress((void**)&wqrl, g_wqrl);
    cudaGetSymbolAddress((void**)&wkrh, g_wkrh); cudaGetSymbolAddress((void**)&wkrl, g_wkrl);
    cudaGetSymbolAddress((void**)&qrelh, g_qrelh); cudaGetSymbolAddress((void**)&qrell, g_qrell);
    cudaGetSymbolAddress((void**)&krelh, g_krelh); cudaGetSymbolAddress((void**)&krell, g_krell);
    cudaGetSymbolAddress((void**)&scores, g_scores);
    cudaGetSymbolAddress((void**)&relp, g_relp); cudaGetSymbolAddress((void**)&mask, g_mask);

    cudaFuncSetAttribute(gemm_qkv, cudaFuncAttributeMaxDynamicSharedMemorySize, GSMEM);
    cudaFuncSetAttribute(gemm_o,   cudaFuncAttributeMaxDynamicSharedMemorySize, GSMEM);
    cudaFuncSetAttribute(flash_mma, cudaFuncAttributeMaxDynamicSharedMemorySize, FSMEM);
    cudaFuncSetAttribute(score_mma, cudaFuncAttributeMaxDynamicSharedMemorySize, RSMEM);
    cudaFuncSetAttribute(rel_mma,   cudaFuncAttributeMaxDynamicSharedMemorySize, RMSMEM);

    static cudaStream_t sSide = nullptr;
    static cudaEvent_t  evFork = nullptr, evJoin = nullptr;
    if (sSide == nullptr) {
        cudaStreamCreateWithFlags(&sSide, cudaStreamNonBlocking);
        cudaEventCreateWithFlags(&evFork, cudaEventDisableTiming);
        cudaEventCreateWithFlags(&evJoin, cudaEventDisableTiming);
    }

    const int nw4 = DD * DD / 4;
    const int nAll = N4H + 3 * N4W;
    const int nRel = N4H + 2 * N4WR;

    // ---- fork: relevance/mask path (+ Wo cvt) on side stream ----
    cudaEventRecord(evFork, 0);
    cudaStreamWaitEvent(sSide, evFork, 0);
    cvt_rel<<<(nRel + 255)/256, 256, 0, sSide>>>(
        (const float4*)relevance, (const float4*)Wqr, (const float4*)Wkr,
        (uint2*)relh, (uint2*)rell, (uint2*)wqrh, (uint2*)wqrl,
        (uint2*)wkrh, (uint2*)wkrl);
    rel_mma<<<dim3(4, MROWS/128), 256, RMSMEM, sSide>>>(
        relh, rell, wqrh, wqrl, wkrh, wkrl, relp);
    rel_reduce<<<(MROWS*64)/256, 256, 0, sSide>>>(relp, qrelh, qrell, krelh, krell);
    score_mma<<<dim3(16, 16, BB), 256, RSMEM, sSide>>>(qrelh, qrell, krelh, krell, scores);
    build_mask<<<dim3(LL, BB), 256, 0, sSide>>>(scores, mask);
    cvt_hi<<<(nw4 + 255)/256, 256, 0, sSide>>>((const float4*)Wo, (uint2*)woh, nw4);
    cudaEventRecord(evJoin, sSide);

    // ---- main stream: merged conversion + QKV ----
    cvt_all<<<(nAll + 255)/256, 256>>>(
        (const float4*)hidden, (const float4*)Wq, (const float4*)Wk, (const float4*)Wv,
        (uint2*)hidh, (uint2*)wqh, (uint2*)wkh, (uint2*)wvh);

    gemm_qkv<<<dim3(DD/256, MROWS/128, 3), 256, GSMEM>>>(
        hidh, wqh, qh, wkh, kh, wvh, vh);

    // ---- join, then attention + output projection ----
    cudaStreamWaitEvent(0, evJoin, 0);
    flash_mma<<<dim3(LL/64, HH, BB), 128, FSMEM>>>(qh, kh, vh, mask, ctxh);
    gemm_o<<<dim3(DD/256, MROWS/128), 256, GSMEM>>>(ctxh, woh, out);
}